// round 3
// baseline (speedup 1.0000x reference)
#include <cuda_runtime.h>
#include <math.h>

#define Bb    8
#define Hh    16
#define DHd   64
#define Ff    16
#define Nsp   196
#define Ntok  3137          // 1 + 16*196
#define DIM   1024
#define BH    (Bb*Hh)       // 128
#define Mrows (Bb*Ntok)     // 25096
#define O3    (3*DIM)       // 3072

// Scratch (device globals; allocation is forbidden).
// Attention output is written IN PLACE into g_q (safe: each q row is fully
// consumed before its overwrite; see per-kernel notes).
__device__ __align__(16) float g_q[(size_t)BH*Ntok*DHd];
__device__ __align__(16) float g_k[(size_t)BH*Ntok*DHd];
__device__ __align__(16) float g_v[(size_t)BH*Ntok*DHd];

// ---------------------------------------------------------------------------
// Kernel 1: qkv = x @ w_qkv^T, scattered into per-head [bh, tok, dh] layout
// ---------------------------------------------------------------------------
__global__ __launch_bounds__(256) void qkv_gemm(const float* __restrict__ X,
                                                const float* __restrict__ W) {
    __shared__ __align__(16) float As[16][128];
    __shared__ __align__(16) float Bs[16][128];
    const int mBase = blockIdx.y * 128;
    const int nBase = blockIdx.x * 128;
    const int tid = threadIdx.x;
    const int tx = tid & 15, ty = tid >> 4;

    // per-thread load row (same row for both float4 slots)
    const int lrow = tid >> 1;
    const int am = mBase + lrow;
    const bool aval = (am < Mrows);
    const float* arow = X + (size_t)(aval ? am : 0) * DIM;
    const float* brow = W + (size_t)(nBase + lrow) * DIM;

    float acc[8][8];
#pragma unroll
    for (int i = 0; i < 8; i++)
#pragma unroll
        for (int j = 0; j < 8; j++) acc[i][j] = 0.f;

    for (int k0 = 0; k0 < DIM; k0 += 16) {
#pragma unroll
        for (int l = 0; l < 2; l++) {
            int idx = tid * 2 + l;
            int cv = (idx & 3) * 4;
            float4 a = make_float4(0.f, 0.f, 0.f, 0.f);
            if (aval) a = *(const float4*)&arow[k0 + cv];
            As[cv + 0][lrow] = a.x; As[cv + 1][lrow] = a.y;
            As[cv + 2][lrow] = a.z; As[cv + 3][lrow] = a.w;
            float4 b = *(const float4*)&brow[k0 + cv];
            Bs[cv + 0][lrow] = b.x; Bs[cv + 1][lrow] = b.y;
            Bs[cv + 2][lrow] = b.z; Bs[cv + 3][lrow] = b.w;
        }
        __syncthreads();
#pragma unroll
        for (int kk = 0; kk < 16; kk++) {
            float a[8], b[8];
            float4 a0 = *(const float4*)&As[kk][ty * 8];
            float4 a1 = *(const float4*)&As[kk][ty * 8 + 4];
            a[0]=a0.x; a[1]=a0.y; a[2]=a0.z; a[3]=a0.w;
            a[4]=a1.x; a[5]=a1.y; a[6]=a1.z; a[7]=a1.w;
            float4 b0 = *(const float4*)&Bs[kk][tx * 8];
            float4 b1 = *(const float4*)&Bs[kk][tx * 8 + 4];
            b[0]=b0.x; b[1]=b0.y; b[2]=b0.z; b[3]=b0.w;
            b[4]=b1.x; b[5]=b1.y; b[6]=b1.z; b[7]=b1.w;
#pragma unroll
            for (int i = 0; i < 8; i++)
#pragma unroll
                for (int j = 0; j < 8; j++) acc[i][j] += a[i] * b[j];
        }
        __syncthreads();
    }

    // scatter epilogue: whole 128-col tile lies inside one of q/k/v
    const int which = nBase >> 10;
    float* dst = (which == 0) ? g_q : (which == 1) ? g_k : g_v;
#pragma unroll
    for (int i = 0; i < 8; i++) {
        int m = mBase + ty * 8 + i;
        if (m >= Mrows) continue;
        int b = m / Ntok;
        int t = m - b * Ntok;
#pragma unroll
        for (int j = 0; j < 8; j++) {
            int o = nBase + tx * 8 + j;
            int rem = o & 1023;
            int h = rem >> 6, dh = rem & 63;
            dst[(((size_t)(b * Hh + h)) * Ntok + t) * DHd + dh] = acc[i][j];
        }
    }
}

// ---------------------------------------------------------------------------
// Kernel 2: spatial attention. 1 CTA per (bh, frame). 196 q rows over 197 keys
// (cls key prepended). 8 warps, 1 warp per q row. Output written in place
// into g_q: each warp fully loads its q row to registers before the store,
// and no other warp ever reads that row's q.
// ---------------------------------------------------------------------------
#define SPK 200   // padded stride for Kt[64][SPK] (conflict-free: lanes read consecutive k)
#define SPV 68    // padded stride for Vs[197][SPV] (16B-aligned, conflict-free column reads)
#define SMEM_ATTN ((64*SPK + 197*SPV + 8*SPK) * sizeof(float))

__global__ __launch_bounds__(256) void attn_spatial() {
    extern __shared__ __align__(16) float sm[];
    float* Kt = sm;                       // [64][SPK]  transposed keys
    float* Vs = sm + 64 * SPK;            // [197][SPV]
    float* Ps = Vs + 197 * SPV;           // [8][SPK]   per-warp probabilities

    const int bid = blockIdx.x;
    const int bh = bid >> 4, fi = bid & 15;
    const int base = 1 + fi * Nsp;
    const float* Kg = g_k + (size_t)bh * Ntok * DHd;
    const float* Vg = g_v + (size_t)bh * Ntok * DHd;
    float* Qg = g_q + (size_t)bh * Ntok * DHd;   // q in, attn out (in place)
    const int tid = threadIdx.x;

    for (int idx = tid; idx < 197 * 16; idx += 256) {
        int key = idx >> 4;
        int d = (idx & 15) * 4;
        int tok = (key == 0) ? 0 : base + key - 1;
        float4 kv = *(const float4*)&Kg[(size_t)tok * DHd + d];
        Kt[(d + 0) * SPK + key] = kv.x; Kt[(d + 1) * SPK + key] = kv.y;
        Kt[(d + 2) * SPK + key] = kv.z; Kt[(d + 3) * SPK + key] = kv.w;
        float4 vv = *(const float4*)&Vg[(size_t)tok * DHd + d];
        *(float4*)&Vs[key * SPV + d] = vv;
    }
    __syncthreads();

    const int warp = tid >> 5, lane = tid & 31;

    for (int r = warp; r < Nsp; r += 8) {
        int tok = base + r;
        float* qr = Qg + (size_t)tok * DHd;
        float q[64];
#pragma unroll
        for (int d = 0; d < 64; d += 4) {
            float4 t4 = *(const float4*)&qr[d];
            q[d] = t4.x; q[d + 1] = t4.y; q[d + 2] = t4.z; q[d + 3] = t4.w;
        }
        float sc[7];
        float mx = -1e30f;
#pragma unroll
        for (int jj = 0; jj < 7; jj++) {
            int k = lane + jj * 32;
            float s = -1e30f;
            if (k < 197) {
                s = 0.f;
#pragma unroll
                for (int d = 0; d < 64; d++) s += q[d] * Kt[d * SPK + k];
                s *= 0.125f;
            }
            sc[jj] = s;
            mx = fmaxf(mx, s);
        }
#pragma unroll
        for (int o = 16; o > 0; o >>= 1)
            mx = fmaxf(mx, __shfl_xor_sync(0xffffffffu, mx, o));
        float sum = 0.f;
#pragma unroll
        for (int jj = 0; jj < 7; jj++) {
            float e = (sc[jj] > -1e29f) ? __expf(sc[jj] - mx) : 0.f;
            sc[jj] = e;
            sum += e;
        }
#pragma unroll
        for (int o = 16; o > 0; o >>= 1)
            sum += __shfl_xor_sync(0xffffffffu, sum, o);
        float inv = 1.f / sum;
#pragma unroll
        for (int jj = 0; jj < 7; jj++) {
            int k = lane + jj * 32;
            if (k < 197) Ps[warp * SPK + k] = sc[jj] * inv;
        }
        __syncwarp();
        float o0 = 0.f, o1 = 0.f;
        for (int k = 0; k < 197; k++) {
            float p = Ps[warp * SPK + k];
            o0 += p * Vs[k * SPV + lane];
            o1 += p * Vs[k * SPV + lane + 32];
        }
        qr[lane] = o0;
        qr[lane + 32] = o1;
        __syncwarp();
    }
}

// ---------------------------------------------------------------------------
// Kernel 3: cls attention. 1 CTA per head-row, cls query over all 3137 keys.
// q[0] staged to smem (sync'd) before the in-place write to g_q token 0.
// ---------------------------------------------------------------------------
__global__ __launch_bounds__(256) void attn_cls() {
    __shared__ __align__(16) float qs[64];
    __shared__ __align__(16) float red[256];
    __shared__ __align__(16) float outp[4][64];
    __shared__ __align__(16) float sc[Ntok];
    const int bh = blockIdx.x;
    const float* Kg = g_k + (size_t)bh * Ntok * DHd;
    const float* Vg = g_v + (size_t)bh * Ntok * DHd;
    const int tid = threadIdx.x;

    if (tid < 16) {
        float4 v = *(const float4*)&g_q[(size_t)bh * Ntok * DHd + tid * 4];
        *(float4*)&qs[tid * 4] = v;
    }
    __syncthreads();

    float lmax = -1e30f;
    for (int k = tid; k < Ntok; k += 256) {
        const float* kr = &Kg[(size_t)k * DHd];
        float s = 0.f;
#pragma unroll
        for (int d = 0; d < 64; d += 4) {
            float4 kv = *(const float4*)&kr[d];
            s += qs[d] * kv.x + qs[d + 1] * kv.y + qs[d + 2] * kv.z + qs[d + 3] * kv.w;
        }
        s *= 0.125f;
        sc[k] = s;
        lmax = fmaxf(lmax, s);
    }
    red[tid] = lmax;
    __syncthreads();
    for (int s2 = 128; s2 > 0; s2 >>= 1) {
        if (tid < s2) red[tid] = fmaxf(red[tid], red[tid + s2]);
        __syncthreads();
    }
    const float mx = red[0];
    __syncthreads();

    float lsum = 0.f;
    for (int k = tid; k < Ntok; k += 256) {
        float e = __expf(sc[k] - mx);
        sc[k] = e;
        lsum += e;
    }
    red[tid] = lsum;
    __syncthreads();
    for (int s2 = 128; s2 > 0; s2 >>= 1) {
        if (tid < s2) red[tid] += red[tid + s2];
        __syncthreads();
    }
    const float inv = 1.f / red[0];

    const int dh = tid & 63, seg = tid >> 6;
    float acc = 0.f;
    for (int k = seg; k < Ntok; k += 4)
        acc += sc[k] * Vg[(size_t)k * DHd + dh];
    outp[seg][dh] = acc;
    __syncthreads();
    if (tid < 64) {
        float o = (outp[0][tid] + outp[1][tid] + outp[2][tid] + outp[3][tid]) * inv;
        g_q[(size_t)bh * Ntok * DHd + tid] = o;
    }
}

// ---------------------------------------------------------------------------
// Kernel 4: out = attn @ w_out^T + b_out (A gathered from per-head layout in g_q)
// ---------------------------------------------------------------------------
__global__ __launch_bounds__(256) void out_gemm(const float* __restrict__ W,
                                                const float* __restrict__ bias,
                                                float* __restrict__ out) {
    __shared__ __align__(16) float As[16][128];
    __shared__ __align__(16) float Bs[16][128];
    const int mBase = blockIdx.y * 128;
    const int nBase = blockIdx.x * 128;
    const int tid = threadIdx.x;
    const int tx = tid & 15, ty = tid >> 4;

    const int lrow = tid >> 1;
    const int am = mBase + lrow;
    const bool aval = (am < Mrows);
    int b = 0, t = 0;
    if (aval) { b = am / Ntok; t = am - b * Ntok; }
    // base pointer for (b, t), head 0
    const float* abase = g_q + (((size_t)(b * Hh)) * Ntok + t) * DHd;
    const float* brow = W + (size_t)(nBase + lrow) * DIM;

    float acc[8][8];
#pragma unroll
    for (int i = 0; i < 8; i++)
#pragma unroll
        for (int j = 0; j < 8; j++) acc[i][j] = 0.f;

    for (int k0 = 0; k0 < DIM; k0 += 16) {
        const int h = k0 >> 6;
        const int dh0 = k0 & 63;
        const float* ah = abase + (size_t)h * Ntok * DHd + dh0;
#pragma unroll
        for (int l = 0; l < 2; l++) {
            int idx = tid * 2 + l;
            int cv = (idx & 3) * 4;
            float4 a = make_float4(0.f, 0.f, 0.f, 0.f);
            if (aval) a = *(const float4*)&ah[cv];
            As[cv + 0][lrow] = a.x; As[cv + 1][lrow] = a.y;
            As[cv + 2][lrow] = a.z; As[cv + 3][lrow] = a.w;
            float4 bw = *(const float4*)&brow[k0 + cv];
            Bs[cv + 0][lrow] = bw.x; Bs[cv + 1][lrow] = bw.y;
            Bs[cv + 2][lrow] = bw.z; Bs[cv + 3][lrow] = bw.w;
        }
        __syncthreads();
#pragma unroll
        for (int kk = 0; kk < 16; kk++) {
            float a[8], bb[8];
            float4 a0 = *(const float4*)&As[kk][ty * 8];
            float4 a1 = *(const float4*)&As[kk][ty * 8 + 4];
            a[0]=a0.x; a[1]=a0.y; a[2]=a0.z; a[3]=a0.w;
            a[4]=a1.x; a[5]=a1.y; a[6]=a1.z; a[7]=a1.w;
            float4 b0 = *(const float4*)&Bs[kk][tx * 8];
            float4 b1 = *(const float4*)&Bs[kk][tx * 8 + 4];
            bb[0]=b0.x; bb[1]=b0.y; bb[2]=b0.z; bb[3]=b0.w;
            bb[4]=b1.x; bb[5]=b1.y; bb[6]=b1.z; bb[7]=b1.w;
#pragma unroll
            for (int i = 0; i < 8; i++)
#pragma unroll
                for (int j = 0; j < 8; j++) acc[i][j] += a[i] * bb[j];
        }
        __syncthreads();
    }

#pragma unroll
    for (int i = 0; i < 8; i++) {
        int m = mBase + ty * 8 + i;
        if (m >= Mrows) continue;
#pragma unroll
        for (int j = 0; j < 8; j++) {
            int o = nBase + tx * 8 + j;
            out[(size_t)m * DIM + o] = acc[i][j] + bias[o];
        }
    }
}

// ---------------------------------------------------------------------------
extern "C" void kernel_launch(void* const* d_in, const int* in_sizes, int n_in,
                              void* d_out, int out_size) {
    const float* x     = (const float*)d_in[0];
    const float* w_qkv = (const float*)d_in[1];
    const float* w_out = (const float*)d_in[2];
    const float* b_out = (const float*)d_in[3];
    (void)in_sizes; (void)n_in; (void)out_size;

    cudaFuncSetAttribute(attn_spatial, cudaFuncAttributeMaxDynamicSharedMemorySize,
                         (int)SMEM_ATTN);

    dim3 g1(O3 / 128, (Mrows + 127) / 128);
    qkv_gemm<<<g1, 256>>>(x, w_qkv);

    attn_spatial<<<BH * Ff, 256, SMEM_ATTN>>>();
    attn_cls<<<BH, 256>>>();

    dim3 g2(DIM / 128, (Mrows + 127) / 128);
    out_gemm<<<g2, 256>>>(w_out, b_out, (float*)d_out);
}

// round 7
// speedup vs baseline: 1.4532x; 1.4532x over previous
#include <cuda_runtime.h>
#include <cuda_bf16.h>
#include <mma.h>
#include <cstdint>
#include <stdint.h>
#include <math.h>

using namespace nvcuda;

#define Bb    8
#define Hh    16
#define DHd   64
#define Ff    16
#define Nsp   196
#define Ntok  3137          // 1 + 16*196
#define DIM   1024
#define BH    (Bb*Hh)       // 128
#define Mrows (Bb*Ntok)     // 25096
#define O3    (3*DIM)       // 3072
#define KDIM  1024
#define KCH   32            // K chunk
#define NCHUNK (KDIM/KCH)   // 32

// ---------------- device scratch (allocation is forbidden) ------------------
// 1.23GB total (known-good footprint). Attention output goes in place into g_q.
__device__ __align__(16) float g_q[(size_t)BH*Ntok*DHd];
__device__ __align__(16) float g_k[(size_t)BH*Ntok*DHd];
__device__ __align__(16) float g_v[(size_t)BH*Ntok*DHd];

// smem tile geometry: 4 tiles (Ahi, Alo, Bhi, Blo), each [128][40] bf16
#define LDT     40
#define TILE_B  (128 * LDT * 2)          // 10240 bytes
#define STAGE_B (4 * TILE_B)             // 40960 bytes
#define GEMM_SMEM (2 * STAGE_B)          // 81920 bytes

// fp32 x8 -> packed bf16 hi (uint4) / lo (uint4)
__device__ __forceinline__ void cvt8(const float4 a, const float4 b, uint4& H, uint4& L) {
    float v[8] = {a.x, a.y, a.z, a.w, b.x, b.y, b.z, b.w};
    unsigned short hs[8], ls[8];
#pragma unroll
    for (int j = 0; j < 8; j++) {
        __nv_bfloat16 h = __float2bfloat16(v[j]);
        __nv_bfloat16 l = __float2bfloat16(v[j] - __bfloat162float(h));
        hs[j] = __bfloat16_as_ushort(h);
        ls[j] = __bfloat16_as_ushort(l);
    }
    H.x = hs[0] | ((uint32_t)hs[1] << 16); H.y = hs[2] | ((uint32_t)hs[3] << 16);
    H.z = hs[4] | ((uint32_t)hs[5] << 16); H.w = hs[6] | ((uint32_t)hs[7] << 16);
    L.x = ls[0] | ((uint32_t)ls[1] << 16); L.y = ls[2] | ((uint32_t)ls[3] << 16);
    L.z = ls[4] | ((uint32_t)ls[5] << 16); L.w = ls[6] | ((uint32_t)ls[7] << 16);
}

// ---------------- wmma GEMM core (templated on A addressing mode) -----------
// mode 0: A row-major [m][1024], chunk k-offset = c*32
// mode 1: A per-head gather from g_q: offset = (c>>1)*Ntok*64 + (c&1)*32
template <int MODE>
__device__ __forceinline__ void gemm_core(char* dsm,
                                          const float* aRow0, const float* aRow1,
                                          const float* bRow0, const float* bRow1,
                                          int g0, int g1,
                                          wmma::fragment<wmma::accumulator,16,16,16,float> acc[4][2]) {
    const int tid = threadIdx.x;
    const int wid = tid >> 5;
    const int wm = wid >> 2, wn = wid & 3;

    // per-thread STS offsets (bytes) inside a tile: seg s -> row r, cols g*8..
    const int r0 = tid >> 2, r1 = (tid + 256) >> 2;
    const uint32_t so0 = (uint32_t)(r0 * LDT + g0 * 8) * 2;
    const uint32_t so1 = (uint32_t)(r1 * LDT + g1 * 8) * 2;

    float4 av[2][2], bv[2][2];

#define LDG_CHUNK(c) do {                                                      \
        size_t ao;                                                             \
        if (MODE == 0) ao = (size_t)(c) * KCH;                                 \
        else ao = (size_t)((c) >> 1) * ((size_t)Ntok * DHd) + ((c) & 1) * 32;  \
        const float* p;                                                        \
        p = aRow0 + ao + g0 * 8;  av[0][0] = *(const float4*)p; av[0][1] = *(const float4*)(p + 4); \
        p = aRow1 + ao + g1 * 8;  av[1][0] = *(const float4*)p; av[1][1] = *(const float4*)(p + 4); \
        size_t bo = (size_t)(c) * KCH;                                         \
        p = bRow0 + bo + g0 * 8;  bv[0][0] = *(const float4*)p; bv[0][1] = *(const float4*)(p + 4); \
        p = bRow1 + bo + g1 * 8;  bv[1][0] = *(const float4*)p; bv[1][1] = *(const float4*)(p + 4); \
    } while (0)

#define STS_CHUNK(buf) do {                                                    \
        char* sb_ = dsm + (buf) * STAGE_B;                                     \
        uint4 H, L;                                                            \
        cvt8(av[0][0], av[0][1], H, L);                                        \
        *(uint4*)(sb_ + so0) = H; *(uint4*)(sb_ + TILE_B + so0) = L;           \
        cvt8(av[1][0], av[1][1], H, L);                                        \
        *(uint4*)(sb_ + so1) = H; *(uint4*)(sb_ + TILE_B + so1) = L;           \
        cvt8(bv[0][0], bv[0][1], H, L);                                        \
        *(uint4*)(sb_ + 2 * TILE_B + so0) = H; *(uint4*)(sb_ + 3 * TILE_B + so0) = L; \
        cvt8(bv[1][0], bv[1][1], H, L);                                        \
        *(uint4*)(sb_ + 2 * TILE_B + so1) = H; *(uint4*)(sb_ + 3 * TILE_B + so1) = L; \
    } while (0)

#pragma unroll
    for (int mt = 0; mt < 4; mt++)
#pragma unroll
        for (int nt = 0; nt < 2; nt++)
            wmma::fill_fragment(acc[mt][nt], 0.0f);

    LDG_CHUNK(0);
    STS_CHUNK(0);
    LDG_CHUNK(1);
    __syncthreads();

    for (int c = 0; c < NCHUNK; c++) {
        const int b = c & 1;
        if (c + 1 < NCHUNK) {
            STS_CHUNK(1 - b);
            if (c + 2 < NCHUNK) LDG_CHUNK(c + 2);
        }
        const __nv_bfloat16* Ah = (const __nv_bfloat16*)(dsm + b * STAGE_B);
        const __nv_bfloat16* Al = (const __nv_bfloat16*)(dsm + b * STAGE_B + TILE_B);
        const __nv_bfloat16* Bh = (const __nv_bfloat16*)(dsm + b * STAGE_B + 2 * TILE_B);
        const __nv_bfloat16* Bl = (const __nv_bfloat16*)(dsm + b * STAGE_B + 3 * TILE_B);
#pragma unroll
        for (int ks = 0; ks < KCH; ks += 16) {
            wmma::fragment<wmma::matrix_b,16,16,16,__nv_bfloat16,wmma::col_major> bh[2], bl[2];
#pragma unroll
            for (int nt = 0; nt < 2; nt++) {
                const int n0 = wn * 32 + nt * 16;
                wmma::load_matrix_sync(bh[nt], Bh + n0 * LDT + ks, LDT);
                wmma::load_matrix_sync(bl[nt], Bl + n0 * LDT + ks, LDT);
            }
#pragma unroll
            for (int mt = 0; mt < 4; mt++) {
                const int m0 = wm * 64 + mt * 16;
                wmma::fragment<wmma::matrix_a,16,16,16,__nv_bfloat16,wmma::row_major> ah, al;
                wmma::load_matrix_sync(ah, Ah + m0 * LDT + ks, LDT);
                wmma::load_matrix_sync(al, Al + m0 * LDT + ks, LDT);
#pragma unroll
                for (int nt = 0; nt < 2; nt++) {
                    wmma::mma_sync(acc[mt][nt], ah, bh[nt], acc[mt][nt]);
                    wmma::mma_sync(acc[mt][nt], al, bh[nt], acc[mt][nt]);
                    wmma::mma_sync(acc[mt][nt], ah, bl[nt], acc[mt][nt]);
                }
            }
        }
        __syncthreads();
    }
#undef LDG_CHUNK
#undef STS_CHUNK

    // stage C tile into smem (reuses stage buffers; all compute done)
    float* Cs = (float*)dsm;            // [128][132]
#pragma unroll
    for (int mt = 0; mt < 4; mt++)
#pragma unroll
        for (int nt = 0; nt < 2; nt++)
            wmma::store_matrix_sync(Cs + (wm * 64 + mt * 16) * 132 + wn * 32 + nt * 16,
                                    acc[mt][nt], 132, wmma::mem_row_major);
    __syncthreads();
}

// ---------------- Kernel 1: qkv GEMM + head scatter -------------------------
__global__ __launch_bounds__(256) void qkv_tc(const float* __restrict__ X,
                                              const float* __restrict__ W) {
    extern __shared__ __align__(16) char dsm[];
    const int tid = threadIdx.x;
    const int mBase = blockIdx.y * 128;
    const int nBase = blockIdx.x * 128;

    const int r0 = tid >> 2, g0 = tid & 3;
    const int r1 = (tid + 256) >> 2, g1 = (tid + 256) & 3;
    int m0 = mBase + r0; if (m0 >= Mrows) m0 = Mrows - 1;
    int m1 = mBase + r1; if (m1 >= Mrows) m1 = Mrows - 1;

    wmma::fragment<wmma::accumulator,16,16,16,float> acc[4][2];
    gemm_core<0>(dsm,
                 X + (size_t)m0 * KDIM, X + (size_t)m1 * KDIM,
                 W + (size_t)(nBase + r0) * KDIM, W + (size_t)(nBase + r1) * KDIM,
                 g0, g1, acc);

    // scatter epilogue from smem C [128][132]
    const float* Cs = (const float*)dsm;
    const int which = nBase >> 10;
    float* dst = (which == 0) ? g_q : (which == 1) ? g_k : g_v;
#pragma unroll
    for (int i = 0; i < 16; i++) {
        int f4 = tid + i * 256;            // 0..4095
        int row = f4 >> 5;
        int col = (f4 & 31) * 4;
        int m = mBase + row;
        if (m >= Mrows) continue;
        int b = m / Ntok, t = m - b * Ntok;
        int o = nBase + col;
        int h = (o & 1023) >> 6, dh = o & 63;
        const float* cp = Cs + row * 132 + col;
        float4 v = make_float4(cp[0], cp[1], cp[2], cp[3]);
        *(float4*)&dst[(((size_t)(b * Hh + h)) * Ntok + t) * DHd + dh] = v;
    }
}

// ---------------- Kernel 4: out GEMM (A gathered from g_q) + bias -----------
__global__ __launch_bounds__(256) void out_tc(const float* __restrict__ W,
                                              const float* __restrict__ bias,
                                              float* __restrict__ out) {
    extern __shared__ __align__(16) char dsm[];
    const int tid = threadIdx.x;
    const int mBase = blockIdx.y * 128;
    const int nBase = blockIdx.x * 128;

    const int r0 = tid >> 2, g0 = tid & 3;
    const int r1 = (tid + 256) >> 2, g1 = (tid + 256) & 3;
    int m0 = mBase + r0; if (m0 >= Mrows) m0 = Mrows - 1;
    int m1 = mBase + r1; if (m1 >= Mrows) m1 = Mrows - 1;
    int b0 = m0 / Ntok, t0 = m0 - b0 * Ntok;
    int b1 = m1 / Ntok, t1 = m1 - b1 * Ntok;

    wmma::fragment<wmma::accumulator,16,16,16,float> acc[4][2];
    gemm_core<1>(dsm,
                 g_q + (((size_t)(b0 * Hh)) * Ntok + t0) * DHd,
                 g_q + (((size_t)(b1 * Hh)) * Ntok + t1) * DHd,
                 W + (size_t)(nBase + r0) * KDIM, W + (size_t)(nBase + r1) * KDIM,
                 g0, g1, acc);

    const float* Cs = (const float*)dsm;
#pragma unroll
    for (int i = 0; i < 16; i++) {
        int f4 = tid + i * 256;
        int row = f4 >> 5;
        int col = (f4 & 31) * 4;
        int m = mBase + row;
        if (m >= Mrows) continue;
        int o = nBase + col;
        const float* cp = Cs + row * 132 + col;
        float4 v;
        v.x = cp[0] + bias[o];
        v.y = cp[1] + bias[o + 1];
        v.z = cp[2] + bias[o + 2];
        v.w = cp[3] + bias[o + 3];
        *(float4*)&out[(size_t)m * DIM + o] = v;
    }
}

// ---------------------------------------------------------------------------
// Kernel 2: spatial attention (fp32, in place into g_q)
// ---------------------------------------------------------------------------
#define SPK 200
#define SPV 68
#define SMEM_ATTN ((64*SPK + 197*SPV + 8*SPK) * sizeof(float))

__global__ __launch_bounds__(256) void attn_spatial() {
    extern __shared__ __align__(16) float sm[];
    float* Kt = sm;
    float* Vs = sm + 64 * SPK;
    float* Ps = Vs + 197 * SPV;

    const int bid = blockIdx.x;
    const int bh = bid >> 4, fi = bid & 15;
    const int base = 1 + fi * Nsp;
    const float* Kg = g_k + (size_t)bh * Ntok * DHd;
    const float* Vg = g_v + (size_t)bh * Ntok * DHd;
    float* Qg = g_q + (size_t)bh * Ntok * DHd;
    const int tid = threadIdx.x;

    for (int idx = tid; idx < 197 * 16; idx += 256) {
        int key = idx >> 4;
        int d = (idx & 15) * 4;
        int tok = (key == 0) ? 0 : base + key - 1;
        float4 kv = *(const float4*)&Kg[(size_t)tok * DHd + d];
        Kt[(d + 0) * SPK + key] = kv.x; Kt[(d + 1) * SPK + key] = kv.y;
        Kt[(d + 2) * SPK + key] = kv.z; Kt[(d + 3) * SPK + key] = kv.w;
        float4 vv = *(const float4*)&Vg[(size_t)tok * DHd + d];
        *(float4*)&Vs[key * SPV + d] = vv;
    }
    __syncthreads();

    const int warp = tid >> 5, lane = tid & 31;

    for (int r = warp; r < Nsp; r += 8) {
        int tok = base + r;
        float* qr = Qg + (size_t)tok * DHd;
        float q[64];
#pragma unroll
        for (int d = 0; d < 64; d += 4) {
            float4 t4 = *(const float4*)&qr[d];
            q[d] = t4.x; q[d + 1] = t4.y; q[d + 2] = t4.z; q[d + 3] = t4.w;
        }
        float sc[7];
        float mx = -1e30f;
#pragma unroll
        for (int jj = 0; jj < 7; jj++) {
            int k = lane + jj * 32;
            float s = -1e30f;
            if (k < 197) {
                s = 0.f;
#pragma unroll
                for (int d = 0; d < 64; d++) s += q[d] * Kt[d * SPK + k];
                s *= 0.125f;
            }
            sc[jj] = s;
            mx = fmaxf(mx, s);
        }
#pragma unroll
        for (int o = 16; o > 0; o >>= 1)
            mx = fmaxf(mx, __shfl_xor_sync(0xffffffffu, mx, o));
        float sum = 0.f;
#pragma unroll
        for (int jj = 0; jj < 7; jj++) {
            float e = (sc[jj] > -1e29f) ? __expf(sc[jj] - mx) : 0.f;
            sc[jj] = e;
            sum += e;
        }
#pragma unroll
        for (int o = 16; o > 0; o >>= 1)
            sum += __shfl_xor_sync(0xffffffffu, sum, o);
        float inv = 1.f / sum;
#pragma unroll
        for (int jj = 0; jj < 7; jj++) {
            int k = lane + jj * 32;
            if (k < 197) Ps[warp * SPK + k] = sc[jj] * inv;
        }
        __syncwarp();
        float o0 = 0.f, o1 = 0.f;
        for (int k = 0; k < 197; k++) {
            float p = Ps[warp * SPK + k];
            o0 += p * Vs[k * SPV + lane];
            o1 += p * Vs[k * SPV + lane + 32];
        }
        qr[lane] = o0;
        qr[lane + 32] = o1;
        __syncwarp();
    }
}

// ---------------------------------------------------------------------------
// Kernel 3: cls attention (fp32, in place into g_q token 0)
// ---------------------------------------------------------------------------
__global__ __launch_bounds__(256) void attn_cls() {
    __shared__ __align__(16) float qs[64];
    __shared__ __align__(16) float red[256];
    __shared__ __align__(16) float outp[4][64];
    __shared__ __align__(16) float sc[Ntok];
    const int bh = blockIdx.x;
    const float* Kg = g_k + (size_t)bh * Ntok * DHd;
    const float* Vg = g_v + (size_t)bh * Ntok * DHd;
    const int tid = threadIdx.x;

    if (tid < 16) {
        float4 v = *(const float4*)&g_q[(size_t)bh * Ntok * DHd + tid * 4];
        *(float4*)&qs[tid * 4] = v;
    }
    __syncthreads();

    float lmax = -1e30f;
    for (int k = tid; k < Ntok; k += 256) {
        const float* kr = &Kg[(size_t)k * DHd];
        float s = 0.f;
#pragma unroll
        for (int d = 0; d < 64; d += 4) {
            float4 kv = *(const float4*)&kr[d];
            s += qs[d] * kv.x + qs[d + 1] * kv.y + qs[d + 2] * kv.z + qs[d + 3] * kv.w;
        }
        s *= 0.125f;
        sc[k] = s;
        lmax = fmaxf(lmax, s);
    }
    red[tid] = lmax;
    __syncthreads();
    for (int s2 = 128; s2 > 0; s2 >>= 1) {
        if (tid < s2) red[tid] = fmaxf(red[tid], red[tid + s2]);
        __syncthreads();
    }
    const float mx = red[0];
    __syncthreads();

    float lsum = 0.f;
    for (int k = tid; k < Ntok; k += 256) {
        float e = __expf(sc[k] - mx);
        sc[k] = e;
        lsum += e;
    }
    red[tid] = lsum;
    __syncthreads();
    for (int s2 = 128; s2 > 0; s2 >>= 1) {
        if (tid < s2) red[tid] += red[tid + s2];
        __syncthreads();
    }
    const float inv = 1.f / red[0];

    const int dh = tid & 63, seg = tid >> 6;
    float acc = 0.f;
    for (int k = seg; k < Ntok; k += 4)
        acc += sc[k] * Vg[(size_t)k * DHd + dh];
    outp[seg][dh] = acc;
    __syncthreads();
    if (tid < 64) {
        float o = (outp[0][tid] + outp[1][tid] + outp[2][tid] + outp[3][tid]) * inv;
        g_q[(size_t)bh * Ntok * DHd + tid] = o;
    }
}

// ---------------------------------------------------------------------------
extern "C" void kernel_launch(void* const* d_in, const int* in_sizes, int n_in,
                              void* d_out, int out_size) {
    const float* x     = (const float*)d_in[0];
    const float* w_qkv = (const float*)d_in[1];
    const float* w_out = (const float*)d_in[2];
    const float* b_out = (const float*)d_in[3];
    (void)in_sizes; (void)n_in; (void)out_size;

    cudaFuncSetAttribute(attn_spatial, cudaFuncAttributeMaxDynamicSharedMemorySize,
                         (int)SMEM_ATTN);
    cudaFuncSetAttribute(qkv_tc, cudaFuncAttributeMaxDynamicSharedMemorySize, GEMM_SMEM);
    cudaFuncSetAttribute(out_tc, cudaFuncAttributeMaxDynamicSharedMemorySize, GEMM_SMEM);

    // qkv projection on tensor cores (HMMA via wmma; fp32->bf16 hi/lo in-kernel)
    dim3 g1(O3 / 128, (Mrows + 127) / 128);
    qkv_tc<<<g1, 256, GEMM_SMEM>>>(x, w_qkv);

    // attention (fp32, in place into g_q)
    attn_spatial<<<BH * Ff, 256, SMEM_ATTN>>>();
    attn_cls<<<BH, 256>>>();

    // output projection on tensor cores (A gathered from per-head layout)
    dim3 g2(DIM / 128, (Mrows + 127) / 128);
    out_tc<<<g2, 256, GEMM_SMEM>>>(w_out, b_out, (float*)d_out);
}

// round 8
// speedup vs baseline: 1.5906x; 1.0945x over previous
#include <cuda_runtime.h>
#include <cuda_bf16.h>
#include <mma.h>
#include <cstdint>
#include <stdint.h>
#include <math.h>

using namespace nvcuda;

#define Bb    8
#define Hh    16
#define DHd   64
#define Ff    16
#define Nsp   196
#define Ntok  3137          // 1 + 16*196
#define DIM   1024
#define BH    (Bb*Hh)       // 128
#define Mrows (Bb*Ntok)     // 25096
#define O3    (3*DIM)       // 3072
#define KDIM  1024
#define KCH   32
#define NCHUNK (KDIM/KCH)   // 32

// ---------------- device scratch (allocation is forbidden) ------------------
__device__ __align__(16) float g_q[(size_t)BH*Ntok*DHd];
__device__ __align__(16) float g_k[(size_t)BH*Ntok*DHd];
__device__ __align__(16) float g_v[(size_t)BH*Ntok*DHd];

// smem stage: Ahi[128][40] Alo[128][40] Bhi[256][40] Blo[256][40] (bf16)
#define LDT     40
#define A_TILE_B (128 * LDT * 2)         // 10240
#define B_TILE_B (256 * LDT * 2)         // 20480
#define OFF_AHI  0
#define OFF_ALO  (A_TILE_B)
#define OFF_BHI  (2 * A_TILE_B)
#define OFF_BLO  (2 * A_TILE_B + B_TILE_B)
#define STAGE_B  (2 * A_TILE_B + 2 * B_TILE_B)   // 61440
#define GEMM_SMEM (2 * STAGE_B)                  // 122880
#define CLD 132                                  // C tile ld (floats)

// fp32 x8 -> packed bf16 hi (uint4) / lo (uint4)
__device__ __forceinline__ void cvt8(const float4 a, const float4 b, uint4& H, uint4& L) {
    float v[8] = {a.x, a.y, a.z, a.w, b.x, b.y, b.z, b.w};
    unsigned short hs[8], ls[8];
#pragma unroll
    for (int j = 0; j < 8; j++) {
        __nv_bfloat16 h = __float2bfloat16(v[j]);
        __nv_bfloat16 l = __float2bfloat16(v[j] - __bfloat162float(h));
        hs[j] = __bfloat16_as_ushort(h);
        ls[j] = __bfloat16_as_ushort(l);
    }
    H.x = hs[0] | ((uint32_t)hs[1] << 16); H.y = hs[2] | ((uint32_t)hs[3] << 16);
    H.z = hs[4] | ((uint32_t)hs[5] << 16); H.w = hs[6] | ((uint32_t)hs[7] << 16);
    L.x = ls[0] | ((uint32_t)ls[1] << 16); L.y = ls[2] | ((uint32_t)ls[3] << 16);
    L.z = ls[4] | ((uint32_t)ls[5] << 16); L.w = ls[6] | ((uint32_t)ls[7] << 16);
}

struct FillCtx {
    const float* aR[2];     // A row bases (+g*8 folded in)
    const float* bR[4];     // B row bases (+g*8 folded in)
    uint32_t soA[2], soB[4];
};

// MODE 0: A k-offset = c*32 ; MODE 1: (c>>1)*Ntok*64 + (c&1)*32 (per-head gather)
template <int MODE>
__device__ __forceinline__ void gemm_core(char* dsm, const FillCtx& fc,
        wmma::fragment<wmma::accumulator,16,16,16,float> acc[4][4]) {
    const int tid = threadIdx.x;
    const int wid = tid >> 5;
    const int wm = wid >> 2, wn = wid & 3;   // 2 x 4 warps, 64x64 tiles

    float4 av[2][2], bv[4][2];

#define LDG_CHUNK(c) do {                                                     \
        size_t ao;                                                            \
        if (MODE == 0) ao = (size_t)(c) * KCH;                                \
        else ao = (size_t)((c) >> 1) * ((size_t)Ntok * DHd) + ((c) & 1) * 32; \
        _Pragma("unroll")                                                     \
        for (int i = 0; i < 2; i++) {                                         \
            const float* p = fc.aR[i] + ao;                                   \
            av[i][0] = *(const float4*)p; av[i][1] = *(const float4*)(p + 4); \
        }                                                                     \
        size_t bo = (size_t)(c) * KCH;                                        \
        _Pragma("unroll")                                                     \
        for (int i = 0; i < 4; i++) {                                         \
            const float* p = fc.bR[i] + bo;                                   \
            bv[i][0] = *(const float4*)p; bv[i][1] = *(const float4*)(p + 4); \
        }                                                                     \
    } while (0)

#define STS_CHUNK(buf) do {                                                   \
        char* sb_ = dsm + (buf) * STAGE_B;                                    \
        uint4 H, L;                                                           \
        _Pragma("unroll")                                                     \
        for (int i = 0; i < 2; i++) {                                         \
            cvt8(av[i][0], av[i][1], H, L);                                   \
            *(uint4*)(sb_ + OFF_AHI + fc.soA[i]) = H;                         \
            *(uint4*)(sb_ + OFF_ALO + fc.soA[i]) = L;                         \
        }                                                                     \
        _Pragma("unroll")                                                     \
        for (int i = 0; i < 4; i++) {                                         \
            cvt8(bv[i][0], bv[i][1], H, L);                                   \
            *(uint4*)(sb_ + OFF_BHI + fc.soB[i]) = H;                         \
            *(uint4*)(sb_ + OFF_BLO + fc.soB[i]) = L;                         \
        }                                                                     \
    } while (0)

#pragma unroll
    for (int mt = 0; mt < 4; mt++)
#pragma unroll
        for (int nt = 0; nt < 4; nt++)
            wmma::fill_fragment(acc[mt][nt], 0.0f);

    LDG_CHUNK(0);
    STS_CHUNK(0);
    LDG_CHUNK(1);
    __syncthreads();

    for (int c = 0; c < NCHUNK; c++) {
        const int b = c & 1;
        const __nv_bfloat16* Ah = (const __nv_bfloat16*)(dsm + b * STAGE_B + OFF_AHI);
        const __nv_bfloat16* Al = (const __nv_bfloat16*)(dsm + b * STAGE_B + OFF_ALO);
        const __nv_bfloat16* Bh = (const __nv_bfloat16*)(dsm + b * STAGE_B + OFF_BHI);
        const __nv_bfloat16* Bl = (const __nv_bfloat16*)(dsm + b * STAGE_B + OFF_BLO);
#pragma unroll
        for (int ks = 0; ks < KCH; ks += 16) {
            wmma::fragment<wmma::matrix_b,16,16,16,__nv_bfloat16,wmma::col_major> bf[4];
            // pass 1: hi*hi + lo*hi
#pragma unroll
            for (int nt = 0; nt < 4; nt++)
                wmma::load_matrix_sync(bf[nt], Bh + (wn * 64 + nt * 16) * LDT + ks, LDT);
#pragma unroll
            for (int mt = 0; mt < 4; mt++) {
                wmma::fragment<wmma::matrix_a,16,16,16,__nv_bfloat16,wmma::row_major> ah, al;
                wmma::load_matrix_sync(ah, Ah + (wm * 64 + mt * 16) * LDT + ks, LDT);
                wmma::load_matrix_sync(al, Al + (wm * 64 + mt * 16) * LDT + ks, LDT);
#pragma unroll
                for (int nt = 0; nt < 4; nt++) {
                    wmma::mma_sync(acc[mt][nt], ah, bf[nt], acc[mt][nt]);
                    wmma::mma_sync(acc[mt][nt], al, bf[nt], acc[mt][nt]);
                }
            }
            // pass 2: hi*lo (reuse bf regs)
#pragma unroll
            for (int nt = 0; nt < 4; nt++)
                wmma::load_matrix_sync(bf[nt], Bl + (wn * 64 + nt * 16) * LDT + ks, LDT);
#pragma unroll
            for (int mt = 0; mt < 4; mt++) {
                wmma::fragment<wmma::matrix_a,16,16,16,__nv_bfloat16,wmma::row_major> ah;
                wmma::load_matrix_sync(ah, Ah + (wm * 64 + mt * 16) * LDT + ks, LDT);
#pragma unroll
                for (int nt = 0; nt < 4; nt++)
                    wmma::mma_sync(acc[mt][nt], ah, bf[nt], acc[mt][nt]);
            }
        }
        if (c + 1 < NCHUNK) {
            STS_CHUNK(1 - b);
            if (c + 2 < NCHUNK) LDG_CHUNK(c + 2);
        }
        __syncthreads();
    }
#undef LDG_CHUNK
#undef STS_CHUNK
}

__device__ __forceinline__ void make_fill_ctx(int tid, int mBase, int nBase,
                                              const float* Abase, size_t aRowStride,
                                              int aIsGather, const float* W, FillCtx& fc) {
    const int r = tid >> 2;
    const int g8 = (tid & 3) * 8;
#pragma unroll
    for (int i = 0; i < 2; i++) {
        int m = mBase + r + i * 64;
        if (m >= Mrows) m = Mrows - 1;
        if (!aIsGather) {
            fc.aR[i] = Abase + (size_t)m * KDIM + g8;
        } else {
            int b = m / Ntok, t = m - b * Ntok;
            fc.aR[i] = Abase + (((size_t)(b * Hh)) * Ntok + t) * DHd + g8;
        }
        fc.soA[i] = (uint32_t)((r + i * 64) * LDT + g8) * 2;
    }
#pragma unroll
    for (int i = 0; i < 4; i++) {
        fc.bR[i] = W + (size_t)(nBase + r + i * 64) * KDIM + g8;
        fc.soB[i] = (uint32_t)((r + i * 64) * LDT + g8) * 2;
    }
    (void)aRowStride;
}

// ---------------- Kernel 1: qkv GEMM + head scatter -------------------------
__global__ __launch_bounds__(256) void qkv_tc(const float* __restrict__ X,
                                              const float* __restrict__ W) {
    extern __shared__ __align__(16) char dsm[];
    const int tid = threadIdx.x;
    const int wid = tid >> 5;
    const int wm = wid >> 2, wn = wid & 3;
    const int mBase = blockIdx.y * 128;
    const int nBase = blockIdx.x * 256;

    FillCtx fc;
    make_fill_ctx(tid, mBase, nBase, X, 0, 0, W, fc);

    wmma::fragment<wmma::accumulator,16,16,16,float> acc[4][4];
    gemm_core<0>(dsm, fc, acc);

    const int which = nBase >> 10;
    float* dst = (which == 0) ? g_q : (which == 1) ? g_k : g_v;
    float* Cs = (float*)dsm;

#pragma unroll
    for (int half = 0; half < 2; half++) {
        __syncthreads();
        if ((wn >> 1) == half) {
#pragma unroll
            for (int mt = 0; mt < 4; mt++)
#pragma unroll
                for (int nt = 0; nt < 4; nt++)
                    wmma::store_matrix_sync(Cs + (wm * 64 + mt * 16) * CLD +
                                            (wn & 1) * 64 + nt * 16,
                                            acc[mt][nt], CLD, wmma::mem_row_major);
        }
        __syncthreads();
#pragma unroll
        for (int i = 0; i < 16; i++) {
            int f4 = tid + i * 256;
            int row = f4 >> 5;
            int col = (f4 & 31) * 4;
            int m = mBase + row;
            if (m >= Mrows) continue;
            int b = m / Ntok, t = m - b * Ntok;
            int o = nBase + half * 128 + col;
            int h = (o & 1023) >> 6, dh = o & 63;
            const float* cp = Cs + row * CLD + col;
            float4 v = make_float4(cp[0], cp[1], cp[2], cp[3]);
            *(float4*)&dst[(((size_t)(b * Hh + h)) * Ntok + t) * DHd + dh] = v;
        }
    }
}

// ---------------- Kernel 4: out GEMM (A gathered from g_q) + bias -----------
__global__ __launch_bounds__(256) void out_tc(const float* __restrict__ W,
                                              const float* __restrict__ bias,
                                              float* __restrict__ out) {
    extern __shared__ __align__(16) char dsm[];
    const int tid = threadIdx.x;
    const int wid = tid >> 5;
    const int wm = wid >> 2, wn = wid & 3;
    const int mBase = blockIdx.y * 128;
    const int nBase = blockIdx.x * 256;

    FillCtx fc;
    make_fill_ctx(tid, mBase, nBase, g_q, 0, 1, W, fc);

    wmma::fragment<wmma::accumulator,16,16,16,float> acc[4][4];
    gemm_core<1>(dsm, fc, acc);

    float* Cs = (float*)dsm;
#pragma unroll
    for (int half = 0; half < 2; half++) {
        __syncthreads();
        if ((wn >> 1) == half) {
#pragma unroll
            for (int mt = 0; mt < 4; mt++)
#pragma unroll
                for (int nt = 0; nt < 4; nt++)
                    wmma::store_matrix_sync(Cs + (wm * 64 + mt * 16) * CLD +
                                            (wn & 1) * 64 + nt * 16,
                                            acc[mt][nt], CLD, wmma::mem_row_major);
        }
        __syncthreads();
#pragma unroll
        for (int i = 0; i < 16; i++) {
            int f4 = tid + i * 256;
            int row = f4 >> 5;
            int col = (f4 & 31) * 4;
            int m = mBase + row;
            if (m >= Mrows) continue;
            int o = nBase + half * 128 + col;
            const float* cp = Cs + row * CLD + col;
            float4 v;
            v.x = cp[0] + bias[o];
            v.y = cp[1] + bias[o + 1];
            v.z = cp[2] + bias[o + 2];
            v.w = cp[3] + bias[o + 3];
            *(float4*)&out[(size_t)m * DIM + o] = v;
        }
    }
}

// ---------------------------------------------------------------------------
// Kernel 2: spatial attention (fp32, in place into g_q)
// ---------------------------------------------------------------------------
#define SPK 200
#define SPV 68
#define SMEM_ATTN ((64*SPK + 197*SPV + 8*SPK) * sizeof(float))

__global__ __launch_bounds__(256) void attn_spatial() {
    extern __shared__ __align__(16) float sm[];
    float* Kt = sm;
    float* Vs = sm + 64 * SPK;
    float* Ps = Vs + 197 * SPV;

    const int bid = blockIdx.x;
    const int bh = bid >> 4, fi = bid & 15;
    const int base = 1 + fi * Nsp;
    const float* Kg = g_k + (size_t)bh * Ntok * DHd;
    const float* Vg = g_v + (size_t)bh * Ntok * DHd;
    float* Qg = g_q + (size_t)bh * Ntok * DHd;
    const int tid = threadIdx.x;

    for (int idx = tid; idx < 197 * 16; idx += 256) {
        int key = idx >> 4;
        int d = (idx & 15) * 4;
        int tok = (key == 0) ? 0 : base + key - 1;
        float4 kv = *(const float4*)&Kg[(size_t)tok * DHd + d];
        Kt[(d + 0) * SPK + key] = kv.x; Kt[(d + 1) * SPK + key] = kv.y;
        Kt[(d + 2) * SPK + key] = kv.z; Kt[(d + 3) * SPK + key] = kv.w;
        float4 vv = *(const float4*)&Vg[(size_t)tok * DHd + d];
        *(float4*)&Vs[key * SPV + d] = vv;
    }
    __syncthreads();

    const int warp = tid >> 5, lane = tid & 31;

    for (int r = warp; r < Nsp; r += 8) {
        int tok = base + r;
        float* qr = Qg + (size_t)tok * DHd;
        float q[64];
#pragma unroll
        for (int d = 0; d < 64; d += 4) {
            float4 t4 = *(const float4*)&qr[d];
            q[d] = t4.x; q[d + 1] = t4.y; q[d + 2] = t4.z; q[d + 3] = t4.w;
        }
        float sc[7];
        float mx = -1e30f;
#pragma unroll
        for (int jj = 0; jj < 7; jj++) {
            int k = lane + jj * 32;
            float s = -1e30f;
            if (k < 197) {
                s = 0.f;
#pragma unroll
                for (int d = 0; d < 64; d++) s += q[d] * Kt[d * SPK + k];
                s *= 0.125f;
            }
            sc[jj] = s;
            mx = fmaxf(mx, s);
        }
#pragma unroll
        for (int o = 16; o > 0; o >>= 1)
            mx = fmaxf(mx, __shfl_xor_sync(0xffffffffu, mx, o));
        float sum = 0.f;
#pragma unroll
        for (int jj = 0; jj < 7; jj++) {
            float e = (sc[jj] > -1e29f) ? __expf(sc[jj] - mx) : 0.f;
            sc[jj] = e;
            sum += e;
        }
#pragma unroll
        for (int o = 16; o > 0; o >>= 1)
            sum += __shfl_xor_sync(0xffffffffu, sum, o);
        float inv = 1.f / sum;
#pragma unroll
        for (int jj = 0; jj < 7; jj++) {
            int k = lane + jj * 32;
            if (k < 197) Ps[warp * SPK + k] = sc[jj] * inv;
        }
        __syncwarp();
        float o0 = 0.f, o1 = 0.f;
        for (int k = 0; k < 197; k++) {
            float p = Ps[warp * SPK + k];
            o0 += p * Vs[k * SPV + lane];
            o1 += p * Vs[k * SPV + lane + 32];
        }
        qr[lane] = o0;
        qr[lane + 32] = o1;
        __syncwarp();
    }
}

// ---------------------------------------------------------------------------
// Kernel 3: cls attention (fp32, in place into g_q token 0)
// ---------------------------------------------------------------------------
__global__ __launch_bounds__(256) void attn_cls() {
    __shared__ __align__(16) float qs[64];
    __shared__ __align__(16) float red[256];
    __shared__ __align__(16) float outp[4][64];
    __shared__ __align__(16) float sc[Ntok];
    const int bh = blockIdx.x;
    const float* Kg = g_k + (size_t)bh * Ntok * DHd;
    const float* Vg = g_v + (size_t)bh * Ntok * DHd;
    const int tid = threadIdx.x;

    if (tid < 16) {
        float4 v = *(const float4*)&g_q[(size_t)bh * Ntok * DHd + tid * 4];
        *(float4*)&qs[tid * 4] = v;
    }
    __syncthreads();

    float lmax = -1e30f;
    for (int k = tid; k < Ntok; k += 256) {
        const float* kr = &Kg[(size_t)k * DHd];
        float s = 0.f;
#pragma unroll
        for (int d = 0; d < 64; d += 4) {
            float4 kv = *(const float4*)&kr[d];
            s += qs[d] * kv.x + qs[d + 1] * kv.y + qs[d + 2] * kv.z + qs[d + 3] * kv.w;
        }
        s *= 0.125f;
        sc[k] = s;
        lmax = fmaxf(lmax, s);
    }
    red[tid] = lmax;
    __syncthreads();
    for (int s2 = 128; s2 > 0; s2 >>= 1) {
        if (tid < s2) red[tid] = fmaxf(red[tid], red[tid + s2]);
        __syncthreads();
    }
    const float mx = red[0];
    __syncthreads();

    float lsum = 0.f;
    for (int k = tid; k < Ntok; k += 256) {
        float e = __expf(sc[k] - mx);
        sc[k] = e;
        lsum += e;
    }
    red[tid] = lsum;
    __syncthreads();
    for (int s2 = 128; s2 > 0; s2 >>= 1) {
        if (tid < s2) red[tid] += red[tid + s2];
        __syncthreads();
    }
    const float inv = 1.f / red[0];

    const int dh = tid & 63, seg = tid >> 6;
    float acc = 0.f;
    for (int k = seg; k < Ntok; k += 4)
        acc += sc[k] * Vg[(size_t)k * DHd + dh];
    outp[seg][dh] = acc;
    __syncthreads();
    if (tid < 64) {
        float o = (outp[0][tid] + outp[1][tid] + outp[2][tid] + outp[3][tid]) * inv;
        g_q[(size_t)bh * Ntok * DHd + tid] = o;
    }
}

// ---------------------------------------------------------------------------
extern "C" void kernel_launch(void* const* d_in, const int* in_sizes, int n_in,
                              void* d_out, int out_size) {
    const float* x     = (const float*)d_in[0];
    const float* w_qkv = (const float*)d_in[1];
    const float* w_out = (const float*)d_in[2];
    const float* b_out = (const float*)d_in[3];
    (void)in_sizes; (void)n_in; (void)out_size;

    cudaFuncSetAttribute(attn_spatial, cudaFuncAttributeMaxDynamicSharedMemorySize,
                         (int)SMEM_ATTN);
    cudaFuncSetAttribute(qkv_tc, cudaFuncAttributeMaxDynamicSharedMemorySize, GEMM_SMEM);
    cudaFuncSetAttribute(out_tc, cudaFuncAttributeMaxDynamicSharedMemorySize, GEMM_SMEM);

    dim3 g1(O3 / 256, (Mrows + 127) / 128);
    qkv_tc<<<g1, 256, GEMM_SMEM>>>(x, w_qkv);

    attn_spatial<<<BH * Ff, 256, SMEM_ATTN>>>();
    attn_cls<<<BH, 256>>>();

    dim3 g2(DIM / 256, (Mrows + 127) / 128);
    out_tc<<<g2, 256, GEMM_SMEM>>>(w_out, b_out, (float*)d_out);
}

// round 9
// speedup vs baseline: 2.1736x; 1.3666x over previous
#include <cuda_runtime.h>
#include <cuda_fp16.h>
#include <mma.h>
#include <cstdint>
#include <stdint.h>
#include <math.h>

using namespace nvcuda;

#define Bb    8
#define Hh    16
#define DHd   64
#define Ff    16
#define Nsp   196
#define Ntok  3137          // 1 + 16*196
#define DIM   1024
#define BH    (Bb*Hh)       // 128
#define Mrows (Bb*Ntok)     // 25096
#define O3    (3*DIM)       // 3072
#define KDIM  1024
#define KCH   32
#define NCHUNK (KDIM/KCH)   // 32

// ---------------- device scratch (allocation is forbidden) ------------------
__device__ __align__(16) float g_q[(size_t)BH*Ntok*DHd];
__device__ __align__(16) float g_k[(size_t)BH*Ntok*DHd];
__device__ __align__(16) float g_v[(size_t)BH*Ntok*DHd];

// smem stage: Ahi[128][40] Alo[128][40] Bhi[256][40]  (fp16)
#define LDT     40
#define A_TILE_B (128 * LDT * 2)         // 10240
#define B_TILE_B (256 * LDT * 2)         // 20480
#define OFF_AHI  0
#define OFF_ALO  (A_TILE_B)
#define OFF_BHI  (2 * A_TILE_B)
#define STAGE_B  (2 * A_TILE_B + B_TILE_B)       // 40960
#define GEMM_SMEM (2 * STAGE_B)                  // 81920
#define CLD 132                                  // C tile ld (floats)

// fp32 x8 -> packed fp16 hi (uint4) + lo (uint4)
__device__ __forceinline__ void cvt8a(const float4 a, const float4 b, uint4& H, uint4& L) {
    float v[8] = {a.x, a.y, a.z, a.w, b.x, b.y, b.z, b.w};
    unsigned short hs[8], ls[8];
#pragma unroll
    for (int j = 0; j < 8; j++) {
        __half h = __float2half(v[j]);
        __half l = __float2half(v[j] - __half2float(h));
        hs[j] = __half_as_ushort(h);
        ls[j] = __half_as_ushort(l);
    }
    H.x = hs[0] | ((uint32_t)hs[1] << 16); H.y = hs[2] | ((uint32_t)hs[3] << 16);
    H.z = hs[4] | ((uint32_t)hs[5] << 16); H.w = hs[6] | ((uint32_t)hs[7] << 16);
    L.x = ls[0] | ((uint32_t)ls[1] << 16); L.y = ls[2] | ((uint32_t)ls[3] << 16);
    L.z = ls[4] | ((uint32_t)ls[5] << 16); L.w = ls[6] | ((uint32_t)ls[7] << 16);
}
// fp32 x8 -> packed fp16 hi only
__device__ __forceinline__ void cvt8b(const float4 a, const float4 b, uint4& H) {
    float v[8] = {a.x, a.y, a.z, a.w, b.x, b.y, b.z, b.w};
    unsigned short hs[8];
#pragma unroll
    for (int j = 0; j < 8; j++)
        hs[j] = __half_as_ushort(__float2half(v[j]));
    H.x = hs[0] | ((uint32_t)hs[1] << 16); H.y = hs[2] | ((uint32_t)hs[3] << 16);
    H.z = hs[4] | ((uint32_t)hs[5] << 16); H.w = hs[6] | ((uint32_t)hs[7] << 16);
}

struct FillCtx {
    const float* aR[2];     // A row bases (+g*8 folded in)
    const float* bR[4];     // B row bases (+g*8 folded in)
    uint32_t soA[2], soB[4];
};

// MODE 0: A k-offset = c*32 ; MODE 1: (c>>1)*Ntok*64 + (c&1)*32 (per-head gather)
template <int MODE>
__device__ __forceinline__ void gemm_core(char* dsm, const FillCtx& fc,
        wmma::fragment<wmma::accumulator,16,16,16,float> acc[4][4]) {
    const int tid = threadIdx.x;
    const int wid = tid >> 5;
    const int wm = wid >> 2, wn = wid & 3;   // 2 x 4 warps, 64x64 tiles

    float4 av[2][2], bv[4][2];

#define LDG_CHUNK(c) do {                                                     \
        size_t ao;                                                            \
        if (MODE == 0) ao = (size_t)(c) * KCH;                                \
        else ao = (size_t)((c) >> 1) * ((size_t)Ntok * DHd) + ((c) & 1) * 32; \
        _Pragma("unroll")                                                     \
        for (int i = 0; i < 2; i++) {                                         \
            const float* p = fc.aR[i] + ao;                                   \
            av[i][0] = *(const float4*)p; av[i][1] = *(const float4*)(p + 4); \
        }                                                                     \
        size_t bo = (size_t)(c) * KCH;                                        \
        _Pragma("unroll")                                                     \
        for (int i = 0; i < 4; i++) {                                         \
            const float* p = fc.bR[i] + bo;                                   \
            bv[i][0] = *(const float4*)p; bv[i][1] = *(const float4*)(p + 4); \
        }                                                                     \
    } while (0)

#define STS_CHUNK(buf) do {                                                   \
        char* sb_ = dsm + (buf) * STAGE_B;                                    \
        uint4 H, L;                                                           \
        _Pragma("unroll")                                                     \
        for (int i = 0; i < 2; i++) {                                         \
            cvt8a(av[i][0], av[i][1], H, L);                                  \
            *(uint4*)(sb_ + OFF_AHI + fc.soA[i]) = H;                         \
            *(uint4*)(sb_ + OFF_ALO + fc.soA[i]) = L;                         \
        }                                                                     \
        _Pragma("unroll")                                                     \
        for (int i = 0; i < 4; i++) {                                         \
            cvt8b(bv[i][0], bv[i][1], H);                                     \
            *(uint4*)(sb_ + OFF_BHI + fc.soB[i]) = H;                         \
        }                                                                     \
    } while (0)

#pragma unroll
    for (int mt = 0; mt < 4; mt++)
#pragma unroll
        for (int nt = 0; nt < 4; nt++)
            wmma::fill_fragment(acc[mt][nt], 0.0f);

    LDG_CHUNK(0);
    STS_CHUNK(0);
    LDG_CHUNK(1);
    __syncthreads();

    for (int c = 0; c < NCHUNK; c++) {
        const int b = c & 1;
        const __half* Ah = (const __half*)(dsm + b * STAGE_B + OFF_AHI);
        const __half* Al = (const __half*)(dsm + b * STAGE_B + OFF_ALO);
        const __half* Bh = (const __half*)(dsm + b * STAGE_B + OFF_BHI);
#pragma unroll
        for (int ks = 0; ks < KCH; ks += 16) {
            wmma::fragment<wmma::matrix_b,16,16,16,__half,wmma::col_major> bf[4];
#pragma unroll
            for (int nt = 0; nt < 4; nt++)
                wmma::load_matrix_sync(bf[nt], Bh + (wn * 64 + nt * 16) * LDT + ks, LDT);
#pragma unroll
            for (int mt = 0; mt < 4; mt++) {
                wmma::fragment<wmma::matrix_a,16,16,16,__half,wmma::row_major> ah, al;
                wmma::load_matrix_sync(ah, Ah + (wm * 64 + mt * 16) * LDT + ks, LDT);
                wmma::load_matrix_sync(al, Al + (wm * 64 + mt * 16) * LDT + ks, LDT);
#pragma unroll
                for (int nt = 0; nt < 4; nt++) {
                    wmma::mma_sync(acc[mt][nt], ah, bf[nt], acc[mt][nt]);
                    wmma::mma_sync(acc[mt][nt], al, bf[nt], acc[mt][nt]);
                }
            }
        }
        if (c + 1 < NCHUNK) {
            STS_CHUNK(1 - b);
            if (c + 2 < NCHUNK) LDG_CHUNK(c + 2);
        }
        __syncthreads();
    }
#undef LDG_CHUNK
#undef STS_CHUNK
}

__device__ __forceinline__ void make_fill_ctx(int tid, int mBase, int nBase,
                                              const float* Abase,
                                              int aIsGather, const float* W, FillCtx& fc) {
    const int r = tid >> 2;
    const int g8 = (tid & 3) * 8;
#pragma unroll
    for (int i = 0; i < 2; i++) {
        int m = mBase + r + i * 64;
        if (m >= Mrows) m = Mrows - 1;
        if (!aIsGather) {
            fc.aR[i] = Abase + (size_t)m * KDIM + g8;
        } else {
            int b = m / Ntok, t = m - b * Ntok;
            fc.aR[i] = Abase + (((size_t)(b * Hh)) * Ntok + t) * DHd + g8;
        }
        fc.soA[i] = (uint32_t)((r + i * 64) * LDT + g8) * 2;
    }
#pragma unroll
    for (int i = 0; i < 4; i++) {
        fc.bR[i] = W + (size_t)(nBase + r + i * 64) * KDIM + g8;
        fc.soB[i] = (uint32_t)((r + i * 64) * LDT + g8) * 2;
    }
}

// ---------------- Kernel 1: qkv GEMM + head scatter -------------------------
__global__ __launch_bounds__(256) void qkv_tc(const float* __restrict__ X,
                                              const float* __restrict__ W) {
    extern __shared__ __align__(16) char dsm[];
    const int tid = threadIdx.x;
    const int wid = tid >> 5;
    const int wm = wid >> 2, wn = wid & 3;
    const int mBase = blockIdx.y * 128;
    const int nBase = blockIdx.x * 256;

    FillCtx fc;
    make_fill_ctx(tid, mBase, nBase, X, 0, W, fc);

    wmma::fragment<wmma::accumulator,16,16,16,float> acc[4][4];
    gemm_core<0>(dsm, fc, acc);

    const int which = nBase >> 10;
    float* dst = (which == 0) ? g_q : (which == 1) ? g_k : g_v;
    float* Cs = (float*)dsm;

#pragma unroll
    for (int half = 0; half < 2; half++) {
        __syncthreads();
        if ((wn >> 1) == half) {
#pragma unroll
            for (int mt = 0; mt < 4; mt++)
#pragma unroll
                for (int nt = 0; nt < 4; nt++)
                    wmma::store_matrix_sync(Cs + (wm * 64 + mt * 16) * CLD +
                                            (wn & 1) * 64 + nt * 16,
                                            acc[mt][nt], CLD, wmma::mem_row_major);
        }
        __syncthreads();
#pragma unroll
        for (int i = 0; i < 16; i++) {
            int f4 = tid + i * 256;
            int row = f4 >> 5;
            int col = (f4 & 31) * 4;
            int m = mBase + row;
            if (m >= Mrows) continue;
            int b = m / Ntok, t = m - b * Ntok;
            int o = nBase + half * 128 + col;
            int h = (o & 1023) >> 6, dh = o & 63;
            const float* cp = Cs + row * CLD + col;
            float4 v = make_float4(cp[0], cp[1], cp[2], cp[3]);
            *(float4*)&dst[(((size_t)(b * Hh + h)) * Ntok + t) * DHd + dh] = v;
        }
    }
}

// ---------------- Kernel 4: out GEMM (A gathered from g_q) + bias -----------
__global__ __launch_bounds__(256) void out_tc(const float* __restrict__ W,
                                              const float* __restrict__ bias,
                                              float* __restrict__ out) {
    extern __shared__ __align__(16) char dsm[];
    const int tid = threadIdx.x;
    const int wid = tid >> 5;
    const int wm = wid >> 2, wn = wid & 3;
    const int mBase = blockIdx.y * 128;
    const int nBase = blockIdx.x * 256;

    FillCtx fc;
    make_fill_ctx(tid, mBase, nBase, g_q, 1, W, fc);

    wmma::fragment<wmma::accumulator,16,16,16,float> acc[4][4];
    gemm_core<1>(dsm, fc, acc);

    float* Cs = (float*)dsm;
#pragma unroll
    for (int half = 0; half < 2; half++) {
        __syncthreads();
        if ((wn >> 1) == half) {
#pragma unroll
            for (int mt = 0; mt < 4; mt++)
#pragma unroll
                for (int nt = 0; nt < 4; nt++)
                    wmma::store_matrix_sync(Cs + (wm * 64 + mt * 16) * CLD +
                                            (wn & 1) * 64 + nt * 16,
                                            acc[mt][nt], CLD, wmma::mem_row_major);
        }
        __syncthreads();
#pragma unroll
        for (int i = 0; i < 16; i++) {
            int f4 = tid + i * 256;
            int row = f4 >> 5;
            int col = (f4 & 31) * 4;
            int m = mBase + row;
            if (m >= Mrows) continue;
            int o = nBase + half * 128 + col;
            const float* cp = Cs + row * CLD + col;
            float4 v;
            v.x = cp[0] + bias[o];
            v.y = cp[1] + bias[o + 1];
            v.z = cp[2] + bias[o + 2];
            v.w = cp[3] + bias[o + 3];
            *(float4*)&out[(size_t)m * DIM + o] = v;
        }
    }
}

// ---------------------------------------------------------------------------
// Kernel 2: spatial attention (fp32, in place into g_q)
// ---------------------------------------------------------------------------
#define SPK 200
#define SPV 68
#define SMEM_ATTN ((64*SPK + 197*SPV + 8*SPK) * sizeof(float))

__global__ __launch_bounds__(256) void attn_spatial() {
    extern __shared__ __align__(16) float sm[];
    float* Kt = sm;
    float* Vs = sm + 64 * SPK;
    float* Ps = Vs + 197 * SPV;

    const int bid = blockIdx.x;
    const int bh = bid >> 4, fi = bid & 15;
    const int base = 1 + fi * Nsp;
    const float* Kg = g_k + (size_t)bh * Ntok * DHd;
    const float* Vg = g_v + (size_t)bh * Ntok * DHd;
    float* Qg = g_q + (size_t)bh * Ntok * DHd;
    const int tid = threadIdx.x;

    for (int idx = tid; idx < 197 * 16; idx += 256) {
        int key = idx >> 4;
        int d = (idx & 15) * 4;
        int tok = (key == 0) ? 0 : base + key - 1;
        float4 kv = *(const float4*)&Kg[(size_t)tok * DHd + d];
        Kt[(d + 0) * SPK + key] = kv.x; Kt[(d + 1) * SPK + key] = kv.y;
        Kt[(d + 2) * SPK + key] = kv.z; Kt[(d + 3) * SPK + key] = kv.w;
        float4 vv = *(const float4*)&Vg[(size_t)tok * DHd + d];
        *(float4*)&Vs[key * SPV + d] = vv;
    }
    __syncthreads();

    const int warp = tid >> 5, lane = tid & 31;

    for (int r = warp; r < Nsp; r += 8) {
        int tok = base + r;
        float* qr = Qg + (size_t)tok * DHd;
        float q[64];
#pragma unroll
        for (int d = 0; d < 64; d += 4) {
            float4 t4 = *(const float4*)&qr[d];
            q[d] = t4.x; q[d + 1] = t4.y; q[d + 2] = t4.z; q[d + 3] = t4.w;
        }
        float sc[7];
        float mx = -1e30f;
#pragma unroll
        for (int jj = 0; jj < 7; jj++) {
            int k = lane + jj * 32;
            float s = -1e30f;
            if (k < 197) {
                s = 0.f;
#pragma unroll
                for (int d = 0; d < 64; d++) s += q[d] * Kt[d * SPK + k];
                s *= 0.125f;
            }
            sc[jj] = s;
            mx = fmaxf(mx, s);
        }
#pragma unroll
        for (int o = 16; o > 0; o >>= 1)
            mx = fmaxf(mx, __shfl_xor_sync(0xffffffffu, mx, o));
        float sum = 0.f;
#pragma unroll
        for (int jj = 0; jj < 7; jj++) {
            float e = (sc[jj] > -1e29f) ? __expf(sc[jj] - mx) : 0.f;
            sc[jj] = e;
            sum += e;
        }
#pragma unroll
        for (int o = 16; o > 0; o >>= 1)
            sum += __shfl_xor_sync(0xffffffffu, sum, o);
        float inv = 1.f / sum;
#pragma unroll
        for (int jj = 0; jj < 7; jj++) {
            int k = lane + jj * 32;
            if (k < 197) Ps[warp * SPK + k] = sc[jj] * inv;
        }
        __syncwarp();
        float o0 = 0.f, o1 = 0.f;
        for (int k = 0; k < 197; k++) {
            float p = Ps[warp * SPK + k];
            o0 += p * Vs[k * SPV + lane];
            o1 += p * Vs[k * SPV + lane + 32];
        }
        qr[lane] = o0;
        qr[lane + 32] = o1;
        __syncwarp();
    }
}

// ---------------------------------------------------------------------------
// Kernel 3: cls attention (fp32, in place into g_q token 0)
// ---------------------------------------------------------------------------
__global__ __launch_bounds__(256) void attn_cls() {
    __shared__ __align__(16) float qs[64];
    __shared__ __align__(16) float red[256];
    __shared__ __align__(16) float outp[4][64];
    __shared__ __align__(16) float sc[Ntok];
    const int bh = blockIdx.x;
    const float* Kg = g_k + (size_t)bh * Ntok * DHd;
    const float* Vg = g_v + (size_t)bh * Ntok * DHd;
    const int tid = threadIdx.x;

    if (tid < 16) {
        float4 v = *(const float4*)&g_q[(size_t)bh * Ntok * DHd + tid * 4];
        *(float4*)&qs[tid * 4] = v;
    }
    __syncthreads();

    float lmax = -1e30f;
    for (int k = tid; k < Ntok; k += 256) {
        const float* kr = &Kg[(size_t)k * DHd];
        float s = 0.f;
#pragma unroll
        for (int d = 0; d < 64; d += 4) {
            float4 kv = *(const float4*)&kr[d];
            s += qs[d] * kv.x + qs[d + 1] * kv.y + qs[d + 2] * kv.z + qs[d + 3] * kv.w;
        }
        s *= 0.125f;
        sc[k] = s;
        lmax = fmaxf(lmax, s);
    }
    red[tid] = lmax;
    __syncthreads();
    for (int s2 = 128; s2 > 0; s2 >>= 1) {
        if (tid < s2) red[tid] = fmaxf(red[tid], red[tid + s2]);
        __syncthreads();
    }
    const float mx = red[0];
    __syncthreads();

    float lsum = 0.f;
    for (int k = tid; k < Ntok; k += 256) {
        float e = __expf(sc[k] - mx);
        sc[k] = e;
        lsum += e;
    }
    red[tid] = lsum;
    __syncthreads();
    for (int s2 = 128; s2 > 0; s2 >>= 1) {
        if (tid < s2) red[tid] += red[tid + s2];
        __syncthreads();
    }
    const float inv = 1.f / red[0];

    const int dh = tid & 63, seg = tid >> 6;
    float acc = 0.f;
    for (int k = seg; k < Ntok; k += 4)
        acc += sc[k] * Vg[(size_t)k * DHd + dh];
    outp[seg][dh] = acc;
    __syncthreads();
    if (tid < 64) {
        float o = (outp[0][tid] + outp[1][tid] + outp[2][tid] + outp[3][tid]) * inv;
        g_q[(size_t)bh * Ntok * DHd + tid] = o;
    }
}

// ---------------------------------------------------------------------------
extern "C" void kernel_launch(void* const* d_in, const int* in_sizes, int n_in,
                              void* d_out, int out_size) {
    const float* x     = (const float*)d_in[0];
    const float* w_qkv = (const float*)d_in[1];
    const float* w_out = (const float*)d_in[2];
    const float* b_out = (const float*)d_in[3];
    (void)in_sizes; (void)n_in; (void)out_size;

    cudaFuncSetAttribute(attn_spatial, cudaFuncAttributeMaxDynamicSharedMemorySize,
                         (int)SMEM_ATTN);
    cudaFuncSetAttribute(qkv_tc, cudaFuncAttributeMaxDynamicSharedMemorySize, GEMM_SMEM);
    cudaFuncSetAttribute(out_tc, cudaFuncAttributeMaxDynamicSharedMemorySize, GEMM_SMEM);

    dim3 g1(O3 / 256, (Mrows + 127) / 128);
    qkv_tc<<<g1, 256, GEMM_SMEM>>>(x, w_qkv);

    attn_spatial<<<BH * Ff, 256, SMEM_ATTN>>>();
    attn_cls<<<BH, 256>>>();

    dim3 g2(DIM / 256, (Mrows + 127) / 128);
    out_tc<<<g2, 256, GEMM_SMEM>>>(w_out, b_out, (float*)d_out);
}

// round 11
// speedup vs baseline: 3.1646x; 1.4559x over previous
#include <cuda_runtime.h>
#include <cuda_fp16.h>
#include <mma.h>
#include <cstdint>
#include <stdint.h>
#include <math.h>

using namespace nvcuda;

#define Bb    8
#define Hh    16
#define DHd   64
#define Ff    16
#define Nsp   196
#define Ntok  3137          // 1 + 16*196
#define DIM   1024
#define BH    (Bb*Hh)       // 128
#define Mrows (Bb*Ntok)     // 25096
#define O3    (3*DIM)       // 3072
#define KDIM  1024
#define KCH   32
#define NCHUNK (KDIM/KCH)   // 32

// ---------------- device scratch (allocation is forbidden) ------------------
__device__ __align__(16) float g_q[(size_t)BH*Ntok*DHd];
__device__ __align__(16) float g_k[(size_t)BH*Ntok*DHd];
__device__ __align__(16) float g_v[(size_t)BH*Ntok*DHd];

// ============================================================================
// Projection GEMMs: 2-term fp16 compensated wmma
// ============================================================================
#define LDT     40
#define A_TILE_B (128 * LDT * 2)
#define B_TILE_B (256 * LDT * 2)
#define OFF_AHI  0
#define OFF_ALO  (A_TILE_B)
#define OFF_BHI  (2 * A_TILE_B)
#define STAGE_B  (2 * A_TILE_B + B_TILE_B)
#define GEMM_SMEM (2 * STAGE_B)
#define CLD 132

__device__ __forceinline__ void cvt8a(const float4 a, const float4 b, uint4& H, uint4& L) {
    float v[8] = {a.x, a.y, a.z, a.w, b.x, b.y, b.z, b.w};
    unsigned short hs[8], ls[8];
#pragma unroll
    for (int j = 0; j < 8; j++) {
        __half h = __float2half(v[j]);
        __half l = __float2half(v[j] - __half2float(h));
        hs[j] = __half_as_ushort(h);
        ls[j] = __half_as_ushort(l);
    }
    H.x = hs[0] | ((uint32_t)hs[1] << 16); H.y = hs[2] | ((uint32_t)hs[3] << 16);
    H.z = hs[4] | ((uint32_t)hs[5] << 16); H.w = hs[6] | ((uint32_t)hs[7] << 16);
    L.x = ls[0] | ((uint32_t)ls[1] << 16); L.y = ls[2] | ((uint32_t)ls[3] << 16);
    L.z = ls[4] | ((uint32_t)ls[5] << 16); L.w = ls[6] | ((uint32_t)ls[7] << 16);
}
__device__ __forceinline__ void cvt8b(const float4 a, const float4 b, uint4& H) {
    float v[8] = {a.x, a.y, a.z, a.w, b.x, b.y, b.z, b.w};
    unsigned short hs[8];
#pragma unroll
    for (int j = 0; j < 8; j++)
        hs[j] = __half_as_ushort(__float2half(v[j]));
    H.x = hs[0] | ((uint32_t)hs[1] << 16); H.y = hs[2] | ((uint32_t)hs[3] << 16);
    H.z = hs[4] | ((uint32_t)hs[5] << 16); H.w = hs[6] | ((uint32_t)hs[7] << 16);
}

struct FillCtx {
    const float* aR[2];
    const float* bR[4];
    uint32_t soA[2], soB[4];
};

template <int MODE>
__device__ __forceinline__ void gemm_core(char* dsm, const FillCtx& fc,
        wmma::fragment<wmma::accumulator,16,16,16,float> acc[4][4]) {
    const int tid = threadIdx.x;
    const int wid = tid >> 5;
    const int wm = wid >> 2, wn = wid & 3;

    float4 av[2][2], bv[4][2];

#define LDG_CHUNK(c) do {                                                     \
        size_t ao;                                                            \
        if (MODE == 0) ao = (size_t)(c) * KCH;                                \
        else ao = (size_t)((c) >> 1) * ((size_t)Ntok * DHd) + ((c) & 1) * 32; \
        _Pragma("unroll")                                                     \
        for (int i = 0; i < 2; i++) {                                         \
            const float* p = fc.aR[i] + ao;                                   \
            av[i][0] = *(const float4*)p; av[i][1] = *(const float4*)(p + 4); \
        }                                                                     \
        size_t bo = (size_t)(c) * KCH;                                        \
        _Pragma("unroll")                                                     \
        for (int i = 0; i < 4; i++) {                                         \
            const float* p = fc.bR[i] + bo;                                   \
            bv[i][0] = *(const float4*)p; bv[i][1] = *(const float4*)(p + 4); \
        }                                                                     \
    } while (0)

#define STS_CHUNK(buf) do {                                                   \
        char* sb_ = dsm + (buf) * STAGE_B;                                    \
        uint4 H, L;                                                           \
        _Pragma("unroll")                                                     \
        for (int i = 0; i < 2; i++) {                                         \
            cvt8a(av[i][0], av[i][1], H, L);                                  \
            *(uint4*)(sb_ + OFF_AHI + fc.soA[i]) = H;                         \
            *(uint4*)(sb_ + OFF_ALO + fc.soA[i]) = L;                         \
        }                                                                     \
        _Pragma("unroll")                                                     \
        for (int i = 0; i < 4; i++) {                                         \
            cvt8b(bv[i][0], bv[i][1], H);                                     \
            *(uint4*)(sb_ + OFF_BHI + fc.soB[i]) = H;                         \
        }                                                                     \
    } while (0)

#pragma unroll
    for (int mt = 0; mt < 4; mt++)
#pragma unroll
        for (int nt = 0; nt < 4; nt++)
            wmma::fill_fragment(acc[mt][nt], 0.0f);

    LDG_CHUNK(0);
    STS_CHUNK(0);
    LDG_CHUNK(1);
    __syncthreads();

    for (int c = 0; c < NCHUNK; c++) {
        const int b = c & 1;
        const __half* Ah = (const __half*)(dsm + b * STAGE_B + OFF_AHI);
        const __half* Al = (const __half*)(dsm + b * STAGE_B + OFF_ALO);
        const __half* Bh = (const __half*)(dsm + b * STAGE_B + OFF_BHI);
#pragma unroll
        for (int ks = 0; ks < KCH; ks += 16) {
            wmma::fragment<wmma::matrix_b,16,16,16,__half,wmma::col_major> bf[4];
#pragma unroll
            for (int nt = 0; nt < 4; nt++)
                wmma::load_matrix_sync(bf[nt], Bh + (wn * 64 + nt * 16) * LDT + ks, LDT);
#pragma unroll
            for (int mt = 0; mt < 4; mt++) {
                wmma::fragment<wmma::matrix_a,16,16,16,__half,wmma::row_major> ah, al;
                wmma::load_matrix_sync(ah, Ah + (wm * 64 + mt * 16) * LDT + ks, LDT);
                wmma::load_matrix_sync(al, Al + (wm * 64 + mt * 16) * LDT + ks, LDT);
#pragma unroll
                for (int nt = 0; nt < 4; nt++) {
                    wmma::mma_sync(acc[mt][nt], ah, bf[nt], acc[mt][nt]);
                    wmma::mma_sync(acc[mt][nt], al, bf[nt], acc[mt][nt]);
                }
            }
        }
        if (c + 1 < NCHUNK) {
            STS_CHUNK(1 - b);
            if (c + 2 < NCHUNK) LDG_CHUNK(c + 2);
        }
        __syncthreads();
    }
#undef LDG_CHUNK
#undef STS_CHUNK
}

__device__ __forceinline__ void make_fill_ctx(int tid, int mBase, int nBase,
                                              const float* Abase,
                                              int aIsGather, const float* W, FillCtx& fc) {
    const int r = tid >> 2;
    const int g8 = (tid & 3) * 8;
#pragma unroll
    for (int i = 0; i < 2; i++) {
        int m = mBase + r + i * 64;
        if (m >= Mrows) m = Mrows - 1;
        if (!aIsGather) {
            fc.aR[i] = Abase + (size_t)m * KDIM + g8;
        } else {
            int b = m / Ntok, t = m - b * Ntok;
            fc.aR[i] = Abase + (((size_t)(b * Hh)) * Ntok + t) * DHd + g8;
        }
        fc.soA[i] = (uint32_t)((r + i * 64) * LDT + g8) * 2;
    }
#pragma unroll
    for (int i = 0; i < 4; i++) {
        fc.bR[i] = W + (size_t)(nBase + r + i * 64) * KDIM + g8;
        fc.soB[i] = (uint32_t)((r + i * 64) * LDT + g8) * 2;
    }
}

__global__ __launch_bounds__(256) void qkv_tc(const float* __restrict__ X,
                                              const float* __restrict__ W) {
    extern __shared__ __align__(16) char dsm[];
    const int tid = threadIdx.x;
    const int wid = tid >> 5;
    const int wm = wid >> 2, wn = wid & 3;
    const int mBase = blockIdx.y * 128;
    const int nBase = blockIdx.x * 256;

    FillCtx fc;
    make_fill_ctx(tid, mBase, nBase, X, 0, W, fc);

    wmma::fragment<wmma::accumulator,16,16,16,float> acc[4][4];
    gemm_core<0>(dsm, fc, acc);

    const int which = nBase >> 10;
    float* dst = (which == 0) ? g_q : (which == 1) ? g_k : g_v;
    float* Cs = (float*)dsm;

#pragma unroll
    for (int half = 0; half < 2; half++) {
        __syncthreads();
        if ((wn >> 1) == half) {
#pragma unroll
            for (int mt = 0; mt < 4; mt++)
#pragma unroll
                for (int nt = 0; nt < 4; nt++)
                    wmma::store_matrix_sync(Cs + (wm * 64 + mt * 16) * CLD +
                                            (wn & 1) * 64 + nt * 16,
                                            acc[mt][nt], CLD, wmma::mem_row_major);
        }
        __syncthreads();
#pragma unroll
        for (int i = 0; i < 16; i++) {
            int f4 = tid + i * 256;
            int row = f4 >> 5;
            int col = (f4 & 31) * 4;
            int m = mBase + row;
            if (m >= Mrows) continue;
            int b = m / Ntok, t = m - b * Ntok;
            int o = nBase + half * 128 + col;
            int h = (o & 1023) >> 6, dh = o & 63;
            const float* cp = Cs + row * CLD + col;
            float4 v = make_float4(cp[0], cp[1], cp[2], cp[3]);
            *(float4*)&dst[(((size_t)(b * Hh + h)) * Ntok + t) * DHd + dh] = v;
        }
    }
}

__global__ __launch_bounds__(256) void out_tc(const float* __restrict__ W,
                                              const float* __restrict__ bias,
                                              float* __restrict__ out) {
    extern __shared__ __align__(16) char dsm[];
    const int tid = threadIdx.x;
    const int wid = tid >> 5;
    const int wm = wid >> 2, wn = wid & 3;
    const int mBase = blockIdx.y * 128;
    const int nBase = blockIdx.x * 256;

    FillCtx fc;
    make_fill_ctx(tid, mBase, nBase, g_q, 1, W, fc);

    wmma::fragment<wmma::accumulator,16,16,16,float> acc[4][4];
    gemm_core<1>(dsm, fc, acc);

    float* Cs = (float*)dsm;
#pragma unroll
    for (int half = 0; half < 2; half++) {
        __syncthreads();
        if ((wn >> 1) == half) {
#pragma unroll
            for (int mt = 0; mt < 4; mt++)
#pragma unroll
                for (int nt = 0; nt < 4; nt++)
                    wmma::store_matrix_sync(Cs + (wm * 64 + mt * 16) * CLD +
                                            (wn & 1) * 64 + nt * 16,
                                            acc[mt][nt], CLD, wmma::mem_row_major);
        }
        __syncthreads();
#pragma unroll
        for (int i = 0; i < 16; i++) {
            int f4 = tid + i * 256;
            int row = f4 >> 5;
            int col = (f4 & 31) * 4;
            int m = mBase + row;
            if (m >= Mrows) continue;
            int o = nBase + half * 128 + col;
            const float* cp = Cs + row * CLD + col;
            float4 v;
            v.x = cp[0] + bias[o];
            v.y = cp[1] + bias[o + 1];
            v.z = cp[2] + bias[o + 2];
            v.w = cp[3] + bias[o + 3];
            *(float4*)&out[(size_t)m * DIM + o] = v;
        }
    }
}

// ============================================================================
// Spatial attention — tensor cores (wmma), panelized, no-max softmax
// ============================================================================
#define AM   208          // padded query rows (13 m-tiles)
#define ALD  72           // fp16 tile ld (Q, K, V, P)
#define SLD  68           // fp32 S/O tile ld
#define KP   64           // keys per panel
#define NPAN 4            // 4*64 = 256 >= 197

#define AOFF_QH 0
#define AOFF_QL (AOFF_QH + AM*ALD*2)
#define AOFF_KH (AOFF_QL + AM*ALD*2)
#define AOFF_VH (AOFF_KH + KP*ALD*2)
#define AOFF_PH (AOFF_VH + KP*ALD*2)
#define AOFF_S  (AOFF_PH + AM*ALD*2)
#define ATTN_SMEM (AOFF_S + AM*SLD*4)     // 164,864 bytes

__device__ __forceinline__ uint2 pack4h(float4 v) {
    unsigned short h0 = __half_as_ushort(__float2half(v.x));
    unsigned short h1 = __half_as_ushort(__float2half(v.y));
    unsigned short h2 = __half_as_ushort(__float2half(v.z));
    unsigned short h3 = __half_as_ushort(__float2half(v.w));
    uint2 r;
    r.x = h0 | ((uint32_t)h1 << 16);
    r.y = h2 | ((uint32_t)h3 << 16);
    return r;
}
__device__ __forceinline__ void pack4hl(float4 v, uint2& H, uint2& L) {
    float f[4] = {v.x, v.y, v.z, v.w};
    unsigned short hs[4], ls[4];
#pragma unroll
    for (int j = 0; j < 4; j++) {
        __half h = __float2half(f[j]);
        __half l = __float2half(f[j] - __half2float(h));
        hs[j] = __half_as_ushort(h);
        ls[j] = __half_as_ushort(l);
    }
    H.x = hs[0] | ((uint32_t)hs[1] << 16); H.y = hs[2] | ((uint32_t)hs[3] << 16);
    L.x = ls[0] | ((uint32_t)ls[1] << 16); L.y = ls[2] | ((uint32_t)ls[3] << 16);
}

__global__ __launch_bounds__(256) void attn_spatial_tc() {
    extern __shared__ __align__(16) char smb[];
    __half* Qh = (__half*)(smb + AOFF_QH);
    __half* Ql = (__half*)(smb + AOFF_QL);
    __half* Kh = (__half*)(smb + AOFF_KH);
    __half* Vh = (__half*)(smb + AOFF_VH);
    __half* Ph = (__half*)(smb + AOFF_PH);
    float*  S  = (float*)(smb + AOFF_S);

    const int bid = blockIdx.x;
    const int bh = bid >> 4, fi = bid & 15;
    const int base = 1 + fi * Nsp;
    const float* Kg = g_k + (size_t)bh * Ntok * DHd;
    const float* Vg = g_v + (size_t)bh * Ntok * DHd;
    float* Qg = g_q + (size_t)bh * Ntok * DHd;
    const int tid = threadIdx.x;
    const int wid = tid >> 5;

    // load Q (196x64) -> fp16 hi/lo; rows 196..207 zero
    for (int idx = tid; idx < AM * 16; idx += 256) {
        int r = idx >> 4;
        int c4 = (idx & 15) * 4;
        float4 v = make_float4(0.f, 0.f, 0.f, 0.f);
        if (r < Nsp) v = *(const float4*)&Qg[(size_t)(base + r) * DHd + c4];
        uint2 H, L;
        pack4hl(v, H, L);
        *(uint2*)&Qh[r * ALD + c4] = H;
        *(uint2*)&Ql[r * ALD + c4] = L;
    }

    float rsum = 0.f;                       // thread r (= tid) owns row r
    wmma::fragment<wmma::accumulator,16,16,16,float> oacc[2][4];
#pragma unroll
    for (int i = 0; i < 2; i++)
#pragma unroll
        for (int nt = 0; nt < 4; nt++)
            wmma::fill_fragment(oacc[i][nt], 0.0f);
    const int mt0 = wid;                    // always < 13
    const int mt1 = 8 + wid;                // valid if < 13

    __syncthreads();

    for (int p = 0; p < NPAN; p++) {
        // load K,V panel (64 keys), zero-pad beyond 197
        for (int idx = tid; idx < KP * 16; idx += 256) {
            int j = idx >> 4;
            int c4 = (idx & 15) * 4;
            int gk = p * KP + j;
            float4 kv = make_float4(0.f, 0.f, 0.f, 0.f);
            float4 vv = make_float4(0.f, 0.f, 0.f, 0.f);
            if (gk < 197) {
                int tok = (gk == 0) ? 0 : base + gk - 1;
                kv = *(const float4*)&Kg[(size_t)tok * DHd + c4];
                vv = *(const float4*)&Vg[(size_t)tok * DHd + c4];
            }
            *(uint2*)&Kh[j * ALD + c4] = pack4h(kv);
            *(uint2*)&Vh[j * ALD + c4] = pack4h(vv);
        }
        __syncthreads();

        // QK: S[208][64] = Q @ K^T  (52 tile jobs over 8 warps)
        for (int job = wid; job < 52; job += 8) {
            int mt = job >> 2, nt = job & 3;
            wmma::fragment<wmma::accumulator,16,16,16,float> sacc;
            wmma::fill_fragment(sacc, 0.0f);
#pragma unroll
            for (int k = 0; k < 4; k++) {
                wmma::fragment<wmma::matrix_a,16,16,16,__half,wmma::row_major> ah, al;
                wmma::fragment<wmma::matrix_b,16,16,16,__half,wmma::col_major> bf;
                wmma::load_matrix_sync(bf, Kh + (nt * 16) * ALD + k * 16, ALD);
                wmma::load_matrix_sync(ah, Qh + (mt * 16) * ALD + k * 16, ALD);
                wmma::load_matrix_sync(al, Ql + (mt * 16) * ALD + k * 16, ALD);
                wmma::mma_sync(sacc, ah, bf, sacc);
                wmma::mma_sync(sacc, al, bf, sacc);
            }
            wmma::store_matrix_sync(S + (mt * 16) * SLD + nt * 16, sacc, SLD,
                                    wmma::mem_row_major);
        }
        __syncthreads();

        // exp (no max-sub; scores are O(1)) + row sums + P fp16
        if (tid < AM) {
            const int r = tid;
            const bool rok = (r < Nsp);
            float lsum = 0.f;
#pragma unroll 4
            for (int j = 0; j < KP; j += 4) {
                float4 s4 = *(const float4*)&S[r * SLD + j];
                int gk = p * KP + j;
                float e0 = (rok && gk + 0 < 197) ? __expf(s4.x * 0.125f) : 0.f;
                float e1 = (rok && gk + 1 < 197) ? __expf(s4.y * 0.125f) : 0.f;
                float e2 = (rok && gk + 2 < 197) ? __expf(s4.z * 0.125f) : 0.f;
                float e3 = (rok && gk + 3 < 197) ? __expf(s4.w * 0.125f) : 0.f;
                lsum += e0 + e1 + e2 + e3;
                uint2 P = pack4h(make_float4(e0, e1, e2, e3));
                *(uint2*)&Ph[r * ALD + j] = P;
            }
            rsum += lsum;
        }
        __syncthreads();

        // AV: O += P_panel @ V_panel (acc in registers)
#pragma unroll
        for (int k = 0; k < 4; k++) {
            wmma::fragment<wmma::matrix_b,16,16,16,__half,wmma::row_major> bf[4];
#pragma unroll
            for (int nt = 0; nt < 4; nt++)
                wmma::load_matrix_sync(bf[nt], Vh + (k * 16) * ALD + nt * 16, ALD);
            wmma::fragment<wmma::matrix_a,16,16,16,__half,wmma::row_major> pa;
            wmma::load_matrix_sync(pa, Ph + (mt0 * 16) * ALD + k * 16, ALD);
#pragma unroll
            for (int nt = 0; nt < 4; nt++)
                wmma::mma_sync(oacc[0][nt], pa, bf[nt], oacc[0][nt]);
            if (mt1 < 13) {
                wmma::load_matrix_sync(pa, Ph + (mt1 * 16) * ALD + k * 16, ALD);
#pragma unroll
                for (int nt = 0; nt < 4; nt++)
                    wmma::mma_sync(oacc[1][nt], pa, bf[nt], oacc[1][nt]);
            }
        }
        __syncthreads();
    }

    // epilogue: O frags -> S smem, normalize by 1/rsum, write in place to g_q
#pragma unroll
    for (int nt = 0; nt < 4; nt++) {
        wmma::store_matrix_sync(S + (mt0 * 16) * SLD + nt * 16, oacc[0][nt], SLD,
                                wmma::mem_row_major);
        if (mt1 < 13)
            wmma::store_matrix_sync(S + (mt1 * 16) * SLD + nt * 16, oacc[1][nt], SLD,
                                    wmma::mem_row_major);
    }
    __syncthreads();
    if (tid < Nsp) {
        const float inv = 1.f / rsum;
        const float* orow = &S[tid * SLD];
        float* dst = &Qg[(size_t)(base + tid) * DHd];
#pragma unroll
        for (int c = 0; c < 64; c += 4) {
            float4 v = *(const float4*)&orow[c];
            v.x *= inv; v.y *= inv; v.z *= inv; v.w *= inv;
            *(float4*)&dst[c] = v;
        }
    }
}

// ---------------------------------------------------------------------------
// cls attention (fp32 SIMT, unchanged)
// ---------------------------------------------------------------------------
__global__ __launch_bounds__(256) void attn_cls() {
    __shared__ __align__(16) float qs[64];
    __shared__ __align__(16) float red[256];
    __shared__ __align__(16) float outp[4][64];
    __shared__ __align__(16) float sc[Ntok];
    const int bh = blockIdx.x;
    const float* Kg = g_k + (size_t)bh * Ntok * DHd;
    const float* Vg = g_v + (size_t)bh * Ntok * DHd;
    const int tid = threadIdx.x;

    if (tid < 16) {
        float4 v = *(const float4*)&g_q[(size_t)bh * Ntok * DHd + tid * 4];
        *(float4*)&qs[tid * 4] = v;
    }
    __syncthreads();

    float lmax = -1e30f;
    for (int k = tid; k < Ntok; k += 256) {
        const float* kr = &Kg[(size_t)k * DHd];
        float s = 0.f;
#pragma unroll
        for (int d = 0; d < 64; d += 4) {
            float4 kv = *(const float4*)&kr[d];
            s += qs[d] * kv.x + qs[d + 1] * kv.y + qs[d + 2] * kv.z + qs[d + 3] * kv.w;
        }
        s *= 0.125f;
        sc[k] = s;
        lmax = fmaxf(lmax, s);
    }
    red[tid] = lmax;
    __syncthreads();
    for (int s2 = 128; s2 > 0; s2 >>= 1) {
        if (tid < s2) red[tid] = fmaxf(red[tid], red[tid + s2]);
        __syncthreads();
    }
    const float mx = red[0];
    __syncthreads();

    float lsum = 0.f;
    for (int k = tid; k < Ntok; k += 256) {
        float e = __expf(sc[k] - mx);
        sc[k] = e;
        lsum += e;
    }
    red[tid] = lsum;
    __syncthreads();
    for (int s2 = 128; s2 > 0; s2 >>= 1) {
        if (tid < s2) red[tid] += red[tid + s2];
        __syncthreads();
    }
    const float inv = 1.f / red[0];

    const int dh = tid & 63, seg = tid >> 6;
    float acc = 0.f;
    for (int k = seg; k < Ntok; k += 4)
        acc += sc[k] * Vg[(size_t)k * DHd + dh];
    outp[seg][dh] = acc;
    __syncthreads();
    if (tid < 64) {
        float o = (outp[0][tid] + outp[1][tid] + outp[2][tid] + outp[3][tid]) * inv;
        g_q[(size_t)bh * Ntok * DHd + tid] = o;
    }
}

// ---------------------------------------------------------------------------
extern "C" void kernel_launch(void* const* d_in, const int* in_sizes, int n_in,
                              void* d_out, int out_size) {
    const float* x     = (const float*)d_in[0];
    const float* w_qkv = (const float*)d_in[1];
    const float* w_out = (const float*)d_in[2];
    const float* b_out = (const float*)d_in[3];
    (void)in_sizes; (void)n_in; (void)out_size;

    cudaFuncSetAttribute(qkv_tc, cudaFuncAttributeMaxDynamicSharedMemorySize, GEMM_SMEM);
    cudaFuncSetAttribute(out_tc, cudaFuncAttributeMaxDynamicSharedMemorySize, GEMM_SMEM);
    cudaFuncSetAttribute(attn_spatial_tc, cudaFuncAttributeMaxDynamicSharedMemorySize,
                         (int)ATTN_SMEM);

    dim3 g1(O3 / 256, (Mrows + 127) / 128);
    qkv_tc<<<g1, 256, GEMM_SMEM>>>(x, w_qkv);

    attn_spatial_tc<<<BH * Ff, 256, ATTN_SMEM>>>();
    attn_cls<<<BH, 256>>>();

    dim3 g2(DIM / 256, (Mrows + 127) / 128);
    out_tc<<<g2, 256, GEMM_SMEM>>>(w_out, b_out, (float*)d_out);
}

// round 16
// speedup vs baseline: 3.2749x; 1.0348x over previous
#include <cuda_runtime.h>
#include <cuda_fp16.h>
#include <mma.h>
#include <cstdint>
#include <stdint.h>
#include <math.h>

using namespace nvcuda;

#define Bb    8
#define Hh    16
#define DHd   64
#define Ff    16
#define Nsp   196
#define Ntok  3137          // 1 + 16*196
#define DIM   1024
#define BH    (Bb*Hh)       // 128
#define Mrows (Bb*Ntok)     // 25096
#define O3    (3*DIM)       // 3072
#define KDIM  1024
#define KCH   32
#define NCHUNK (KDIM/KCH)   // 32

// ---------------- device scratch (allocation is forbidden) ------------------
// NOTE: these are ONLY referenced from device code (host-side use of __device__
// symbols is invalid — it passes the host shadow address; caused R12-R15 fails).
__device__ __align__(16) float g_q[(size_t)BH*Ntok*DHd];
__device__ __align__(16) float g_k[(size_t)BH*Ntok*DHd];   // reused as ahi/alo after attn
__device__ __align__(16) float g_v[(size_t)BH*Ntok*DHd];
__device__ __align__(16) __half g_xh[(size_t)Mrows*KDIM];  // 51.4MB
__device__ __align__(16) __half g_xl[(size_t)Mrows*KDIM];  // 51.4MB
__device__ __align__(16) __half g_wqh[(size_t)O3*KDIM];    // 6.3MB
__device__ __align__(16) __half g_woh[(size_t)DIM*KDIM];   // 2.1MB

// ---------------- helpers ---------------------------------------------------
__device__ __forceinline__ uint32_t smem_u32(const void* p) {
    uint32_t a;
    asm("{ .reg .u64 t; cvta.to.shared.u64 t, %1; cvt.u32.u64 %0, t; }"
        : "=r"(a) : "l"(p));
    return a;
}
__device__ __forceinline__ void cp16(uint32_t dst, const void* src) {
    asm volatile("cp.async.cg.shared.global [%0], [%1], 16;" :: "r"(dst), "l"(src));
}
#define CP_COMMIT() asm volatile("cp.async.commit_group;" ::: "memory")
#define CP_WAIT1()  asm volatile("cp.async.wait_group 1;" ::: "memory")
#define CP_WAIT0()  asm volatile("cp.async.wait_group 0;" ::: "memory")

__device__ __forceinline__ void pack8hl(const float4 a, const float4 b, uint4& H, uint4& L) {
    float v[8] = {a.x, a.y, a.z, a.w, b.x, b.y, b.z, b.w};
    unsigned short hs[8], ls[8];
#pragma unroll
    for (int j = 0; j < 8; j++) {
        __half h = __float2half(v[j]);
        __half l = __float2half(v[j] - __half2float(h));
        hs[j] = __half_as_ushort(h);
        ls[j] = __half_as_ushort(l);
    }
    H.x = hs[0] | ((uint32_t)hs[1] << 16); H.y = hs[2] | ((uint32_t)hs[3] << 16);
    H.z = hs[4] | ((uint32_t)hs[5] << 16); H.w = hs[6] | ((uint32_t)hs[7] << 16);
    L.x = ls[0] | ((uint32_t)ls[1] << 16); L.y = ls[2] | ((uint32_t)ls[3] << 16);
    L.z = ls[4] | ((uint32_t)ls[5] << 16); L.w = ls[6] | ((uint32_t)ls[7] << 16);
}
__device__ __forceinline__ uint4 pack8h(const float4 a, const float4 b) {
    float v[8] = {a.x, a.y, a.z, a.w, b.x, b.y, b.z, b.w};
    unsigned short hs[8];
#pragma unroll
    for (int j = 0; j < 8; j++)
        hs[j] = __half_as_ushort(__float2half(v[j]));
    uint4 H;
    H.x = hs[0] | ((uint32_t)hs[1] << 16); H.y = hs[2] | ((uint32_t)hs[3] << 16);
    H.z = hs[4] | ((uint32_t)hs[5] << 16); H.w = hs[6] | ((uint32_t)hs[7] << 16);
    return H;
}

// ---------------- conversion kernels (globals referenced in DEVICE code) ----
__global__ __launch_bounds__(256) void conv_x(const float* __restrict__ s) {
    size_t i = ((size_t)blockIdx.x * 256 + threadIdx.x) * 8;
    if (i >= (size_t)Mrows * KDIM) return;
    float4 a = *(const float4*)(s + i);
    float4 b = *(const float4*)(s + i + 4);
    uint4 H, L;
    pack8hl(a, b, H, L);
    *(uint4*)(g_xh + i) = H;
    *(uint4*)(g_xl + i) = L;
}
__global__ __launch_bounds__(256) void conv_wq(const float* __restrict__ s) {
    size_t i = ((size_t)blockIdx.x * 256 + threadIdx.x) * 8;
    if (i >= (size_t)O3 * KDIM) return;
    float4 a = *(const float4*)(s + i);
    float4 b = *(const float4*)(s + i + 4);
    *(uint4*)(g_wqh + i) = pack8h(a, b);
}
__global__ __launch_bounds__(256) void conv_wo(const float* __restrict__ s) {
    size_t i = ((size_t)blockIdx.x * 256 + threadIdx.x) * 8;
    if (i >= (size_t)DIM * KDIM) return;
    float4 a = *(const float4*)(s + i);
    float4 b = *(const float4*)(s + i + 4);
    *(uint4*)(g_woh + i) = pack8h(a, b);
}
// gather attention output (per-head layout in g_q) -> row-major hi/lo in g_k
__global__ __launch_bounds__(256) void conv_attn() {
    __half* ahi = reinterpret_cast<__half*>(g_k);
    __half* alo = ahi + (size_t)Mrows * KDIM;
    size_t idx = ((size_t)blockIdx.x * 256 + threadIdx.x) * 8;
    if (idx >= (size_t)Mrows * KDIM) return;
    int m = (int)(idx >> 10);
    int o = (int)(idx & 1023);
    int b = m / Ntok, t = m - b * Ntok;
    int h = o >> 6, dh = o & 63;
    const float* src = g_q + (((size_t)(b * Hh + h)) * Ntok + t) * DHd + dh;
    float4 a = *(const float4*)src;
    float4 c = *(const float4*)(src + 4);
    uint4 H, L;
    pack8hl(a, c, H, L);
    *(uint4*)(ahi + idx) = H;
    *(uint4*)(alo + idx) = L;
}

// ============================================================================
// Projection GEMMs: pure cp.async mainloop (pre-converted fp16 operands)
// ============================================================================
#define LDT     40
#define A_TILE_B (128 * LDT * 2)                 // 10240
#define B_TILE_B (256 * LDT * 2)                 // 20480
#define OFF_AHI  0
#define OFF_ALO  (A_TILE_B)
#define OFF_BHI  (2 * A_TILE_B)
#define STAGE_B  (2 * A_TILE_B + B_TILE_B)       // 40960
#define GEMM_SMEM (2 * STAGE_B)                  // 81920
#define CLD 132

#define GEMM_FILL(buf, c) do {                                                \
        uint32_t sb_ = smb + (buf) * STAGE_B;                                 \
        int ko_ = (c) * KCH;                                                  \
        cp16(sb_ + OFF_AHI + soA0_, a0h_ + ko_);                              \
        cp16(sb_ + OFF_AHI + soA1_, a1h_ + ko_);                              \
        cp16(sb_ + OFF_ALO + soA0_, a0l_ + ko_);                              \
        cp16(sb_ + OFF_ALO + soA1_, a1l_ + ko_);                              \
        _Pragma("unroll")                                                     \
        for (int i_ = 0; i_ < 4; i_++)                                        \
            cp16(sb_ + OFF_BHI + soA0_ + (uint32_t)i_ * (64 * LDT * 2),       \
                 b0_ + ko_ + (size_t)i_ * 64 * KDIM);                         \
        CP_COMMIT();                                                          \
    } while (0)

// Declares and fills wmma accumulators acc[4][4] over a 128x256 C tile.
// Requires in scope: tid, wid, wm, wn, mBase, nBase, dsm.  A is row-major
// [m][1024] fp16 hi/lo; B is row-major [n][1024] fp16.
#define GEMM_MAINLOOP(AhG, AlG, BhG)                                          \
    const uint32_t smb = smem_u32(dsm);                                       \
    const int r_ = tid >> 2;                                                  \
    const int g8_ = (tid & 3) * 8;                                            \
    int ra0_ = mBase + r_;       if (ra0_ >= Mrows) ra0_ = Mrows - 1;         \
    int ra1_ = mBase + r_ + 64;  if (ra1_ >= Mrows) ra1_ = Mrows - 1;         \
    const __half* a0h_ = (AhG) + (size_t)ra0_ * KDIM + g8_;                   \
    const __half* a1h_ = (AhG) + (size_t)ra1_ * KDIM + g8_;                   \
    const __half* a0l_ = (AlG) + (size_t)ra0_ * KDIM + g8_;                   \
    const __half* a1l_ = (AlG) + (size_t)ra1_ * KDIM + g8_;                   \
    const __half* b0_ = (BhG) + (size_t)(nBase + r_) * KDIM + g8_;            \
    const uint32_t soA0_ = (uint32_t)(r_ * LDT + g8_) * 2;                    \
    const uint32_t soA1_ = soA0_ + 64 * LDT * 2;                              \
    wmma::fragment<wmma::accumulator,16,16,16,float> acc[4][4];               \
    _Pragma("unroll")                                                         \
    for (int mt = 0; mt < 4; mt++)                                            \
        _Pragma("unroll")                                                     \
        for (int nt = 0; nt < 4; nt++)                                        \
            wmma::fill_fragment(acc[mt][nt], 0.0f);                           \
    GEMM_FILL(0, 0);                                                          \
    GEMM_FILL(1, 1);                                                          \
    for (int c = 0; c < NCHUNK; c++) {                                        \
        const int b = c & 1;                                                  \
        if (c < NCHUNK - 1) CP_WAIT1(); else CP_WAIT0();                      \
        __syncthreads();                                                      \
        const __half* Ah = (const __half*)(dsm + b * STAGE_B + OFF_AHI);      \
        const __half* Al = (const __half*)(dsm + b * STAGE_B + OFF_ALO);      \
        const __half* Bh = (const __half*)(dsm + b * STAGE_B + OFF_BHI);      \
        _Pragma("unroll")                                                     \
        for (int ks = 0; ks < KCH; ks += 16) {                                \
            wmma::fragment<wmma::matrix_b,16,16,16,__half,wmma::col_major> bf[4]; \
            _Pragma("unroll")                                                 \
            for (int nt = 0; nt < 4; nt++)                                    \
                wmma::load_matrix_sync(bf[nt], Bh + (wn * 64 + nt * 16) * LDT + ks, LDT); \
            _Pragma("unroll")                                                 \
            for (int mt = 0; mt < 4; mt++) {                                  \
                wmma::fragment<wmma::matrix_a,16,16,16,__half,wmma::row_major> ah, al; \
                wmma::load_matrix_sync(ah, Ah + (wm * 64 + mt * 16) * LDT + ks, LDT); \
                wmma::load_matrix_sync(al, Al + (wm * 64 + mt * 16) * LDT + ks, LDT); \
                _Pragma("unroll")                                             \
                for (int nt = 0; nt < 4; nt++) {                              \
                    wmma::mma_sync(acc[mt][nt], ah, bf[nt], acc[mt][nt]);     \
                    wmma::mma_sync(acc[mt][nt], al, bf[nt], acc[mt][nt]);     \
                }                                                             \
            }                                                                 \
        }                                                                     \
        __syncthreads();                                                      \
        if (c + 2 < NCHUNK) GEMM_FILL(b, c + 2);                              \
    }

// ---------------- Kernel: qkv GEMM + head scatter ---------------------------
__global__ __launch_bounds__(256) void qkv_tc() {
    extern __shared__ __align__(16) char dsm[];
    const int tid = threadIdx.x;
    const int wid = tid >> 5;
    const int wm = wid >> 2, wn = wid & 3;
    const int mBase = blockIdx.y * 128;
    const int nBase = blockIdx.x * 256;

    GEMM_MAINLOOP(g_xh, g_xl, g_wqh)

    const int which = nBase >> 10;
    float* dst = (which == 0) ? g_q : (which == 1) ? g_k : g_v;
    float* Cs = (float*)dsm;

#pragma unroll
    for (int half = 0; half < 2; half++) {
        __syncthreads();
        if ((wn >> 1) == half) {
#pragma unroll
            for (int mt = 0; mt < 4; mt++)
#pragma unroll
                for (int nt = 0; nt < 4; nt++)
                    wmma::store_matrix_sync(Cs + (wm * 64 + mt * 16) * CLD +
                                            (wn & 1) * 64 + nt * 16,
                                            acc[mt][nt], CLD, wmma::mem_row_major);
        }
        __syncthreads();
#pragma unroll
        for (int i = 0; i < 16; i++) {
            int f4 = tid + i * 256;
            int row = f4 >> 5;
            int col = (f4 & 31) * 4;
            int m = mBase + row;
            if (m >= Mrows) continue;
            int b = m / Ntok, t = m - b * Ntok;
            int o = nBase + half * 128 + col;
            int h = (o & 1023) >> 6, dh = o & 63;
            const float* cp = Cs + row * CLD + col;
            float4 v = make_float4(cp[0], cp[1], cp[2], cp[3]);
            *(float4*)&dst[(((size_t)(b * Hh + h)) * Ntok + t) * DHd + dh] = v;
        }
    }
}

// ---------------- Kernel: out GEMM (A = conv_attn output in g_k) + bias -----
__global__ __launch_bounds__(256) void out_tc(const float* __restrict__ bias,
                                              float* __restrict__ out) {
    extern __shared__ __align__(16) char dsm[];
    const int tid = threadIdx.x;
    const int wid = tid >> 5;
    const int wm = wid >> 2, wn = wid & 3;
    const int mBase = blockIdx.y * 128;
    const int nBase = blockIdx.x * 256;

    const __half* ahi = reinterpret_cast<const __half*>(g_k);
    const __half* alo = ahi + (size_t)Mrows * KDIM;

    GEMM_MAINLOOP(ahi, alo, g_woh)

    float* Cs = (float*)dsm;
#pragma unroll
    for (int half = 0; half < 2; half++) {
        __syncthreads();
        if ((wn >> 1) == half) {
#pragma unroll
            for (int mt = 0; mt < 4; mt++)
#pragma unroll
                for (int nt = 0; nt < 4; nt++)
                    wmma::store_matrix_sync(Cs + (wm * 64 + mt * 16) * CLD +
                                            (wn & 1) * 64 + nt * 16,
                                            acc[mt][nt], CLD, wmma::mem_row_major);
        }
        __syncthreads();
#pragma unroll
        for (int i = 0; i < 16; i++) {
            int f4 = tid + i * 256;
            int row = f4 >> 5;
            int col = (f4 & 31) * 4;
            int m = mBase + row;
            if (m >= Mrows) continue;
            int o = nBase + half * 128 + col;
            const float* cp = Cs + row * CLD + col;
            float4 v;
            v.x = cp[0] + bias[o];
            v.y = cp[1] + bias[o + 1];
            v.z = cp[2] + bias[o + 2];
            v.w = cp[3] + bias[o + 3];
            *(float4*)&out[(size_t)m * DIM + o] = v;
        }
    }
}

// ============================================================================
// Spatial attention — tensor cores (wmma), panelized, no-max softmax
// ============================================================================
#define AM   208
#define ALD  72
#define SLD  68
#define KP   64
#define NPAN 4

#define AOFF_QH 0
#define AOFF_QL (AOFF_QH + AM*ALD*2)
#define AOFF_KH (AOFF_QL + AM*ALD*2)
#define AOFF_VH (AOFF_KH + KP*ALD*2)
#define AOFF_PH (AOFF_VH + KP*ALD*2)
#define AOFF_S  (AOFF_PH + AM*ALD*2)
#define ATTN_SMEM (AOFF_S + AM*SLD*4)

__device__ __forceinline__ uint2 pack4h(float4 v) {
    unsigned short h0 = __half_as_ushort(__float2half(v.x));
    unsigned short h1 = __half_as_ushort(__float2half(v.y));
    unsigned short h2 = __half_as_ushort(__float2half(v.z));
    unsigned short h3 = __half_as_ushort(__float2half(v.w));
    uint2 r;
    r.x = h0 | ((uint32_t)h1 << 16);
    r.y = h2 | ((uint32_t)h3 << 16);
    return r;
}
__device__ __forceinline__ void pack4hl(float4 v, uint2& H, uint2& L) {
    float f[4] = {v.x, v.y, v.z, v.w};
    unsigned short hs[4], ls[4];
#pragma unroll
    for (int j = 0; j < 4; j++) {
        __half h = __float2half(f[j]);
        __half l = __float2half(f[j] - __half2float(h));
        hs[j] = __half_as_ushort(h);
        ls[j] = __half_as_ushort(l);
    }
    H.x = hs[0] | ((uint32_t)hs[1] << 16); H.y = hs[2] | ((uint32_t)hs[3] << 16);
    L.x = ls[0] | ((uint32_t)ls[1] << 16); L.y = ls[2] | ((uint32_t)ls[3] << 16);
}

__global__ __launch_bounds__(256) void attn_spatial_tc() {
    extern __shared__ __align__(16) char smb[];
    __half* Qh = (__half*)(smb + AOFF_QH);
    __half* Ql = (__half*)(smb + AOFF_QL);
    __half* Kh = (__half*)(smb + AOFF_KH);
    __half* Vh = (__half*)(smb + AOFF_VH);
    __half* Ph = (__half*)(smb + AOFF_PH);
    float*  S  = (float*)(smb + AOFF_S);

    const int bid = blockIdx.x;
    const int bh = bid >> 4, fi = bid & 15;
    const int base = 1 + fi * Nsp;
    const float* Kg = g_k + (size_t)bh * Ntok * DHd;
    const float* Vg = g_v + (size_t)bh * Ntok * DHd;
    float* Qg = g_q + (size_t)bh * Ntok * DHd;
    const int tid = threadIdx.x;
    const int wid = tid >> 5;

    for (int idx = tid; idx < AM * 16; idx += 256) {
        int r = idx >> 4;
        int c4 = (idx & 15) * 4;
        float4 v = make_float4(0.f, 0.f, 0.f, 0.f);
        if (r < Nsp) v = *(const float4*)&Qg[(size_t)(base + r) * DHd + c4];
        uint2 H, L;
        pack4hl(v, H, L);
        *(uint2*)&Qh[r * ALD + c4] = H;
        *(uint2*)&Ql[r * ALD + c4] = L;
    }

    float rsum = 0.f;
    wmma::fragment<wmma::accumulator,16,16,16,float> oacc[2][4];
#pragma unroll
    for (int i = 0; i < 2; i++)
#pragma unroll
        for (int nt = 0; nt < 4; nt++)
            wmma::fill_fragment(oacc[i][nt], 0.0f);
    const int mt0 = wid;
    const int mt1 = 8 + wid;

    __syncthreads();

    for (int p = 0; p < NPAN; p++) {
        for (int idx = tid; idx < KP * 16; idx += 256) {
            int j = idx >> 4;
            int c4 = (idx & 15) * 4;
            int gk = p * KP + j;
            float4 kv = make_float4(0.f, 0.f, 0.f, 0.f);
            float4 vv = make_float4(0.f, 0.f, 0.f, 0.f);
            if (gk < 197) {
                int tok = (gk == 0) ? 0 : base + gk - 1;
                kv = *(const float4*)&Kg[(size_t)tok * DHd + c4];
                vv = *(const float4*)&Vg[(size_t)tok * DHd + c4];
            }
            *(uint2*)&Kh[j * ALD + c4] = pack4h(kv);
            *(uint2*)&Vh[j * ALD + c4] = pack4h(vv);
        }
        __syncthreads();

        for (int job = wid; job < 52; job += 8) {
            int mt = job >> 2, nt = job & 3;
            wmma::fragment<wmma::accumulator,16,16,16,float> sacc;
            wmma::fill_fragment(sacc, 0.0f);
#pragma unroll
            for (int k = 0; k < 4; k++) {
                wmma::fragment<wmma::matrix_a,16,16,16,__half,wmma::row_major> ah, al;
                wmma::fragment<wmma::matrix_b,16,16,16,__half,wmma::col_major> bf;
                wmma::load_matrix_sync(bf, Kh + (nt * 16) * ALD + k * 16, ALD);
                wmma::load_matrix_sync(ah, Qh + (mt * 16) * ALD + k * 16, ALD);
                wmma::load_matrix_sync(al, Ql + (mt * 16) * ALD + k * 16, ALD);
                wmma::mma_sync(sacc, ah, bf, sacc);
                wmma::mma_sync(sacc, al, bf, sacc);
            }
            wmma::store_matrix_sync(S + (mt * 16) * SLD + nt * 16, sacc, SLD,
                                    wmma::mem_row_major);
        }
        __syncthreads();

        if (tid < AM) {
            const int r = tid;
            const bool rok = (r < Nsp);
            float lsum = 0.f;
#pragma unroll 4
            for (int j = 0; j < KP; j += 4) {
                float4 s4 = *(const float4*)&S[r * SLD + j];
                int gk = p * KP + j;
                float e0 = (rok && gk + 0 < 197) ? __expf(s4.x * 0.125f) : 0.f;
                float e1 = (rok && gk + 1 < 197) ? __expf(s4.y * 0.125f) : 0.f;
                float e2 = (rok && gk + 2 < 197) ? __expf(s4.z * 0.125f) : 0.f;
                float e3 = (rok && gk + 3 < 197) ? __expf(s4.w * 0.125f) : 0.f;
                lsum += e0 + e1 + e2 + e3;
                uint2 P = pack4h(make_float4(e0, e1, e2, e3));
                *(uint2*)&Ph[r * ALD + j] = P;
            }
            rsum += lsum;
        }
        __syncthreads();

#pragma unroll
        for (int k = 0; k < 4; k++) {
            wmma::fragment<wmma::matrix_b,16,16,16,__half,wmma::row_major> bf[4];
#pragma unroll
            for (int nt = 0; nt < 4; nt++)
                wmma::load_matrix_sync(bf[nt], Vh + (k * 16) * ALD + nt * 16, ALD);
            wmma::fragment<wmma::matrix_a,16,16,16,__half,wmma::row_major> pa;
            wmma::load_matrix_sync(pa, Ph + (mt0 * 16) * ALD + k * 16, ALD);
#pragma unroll
            for (int nt = 0; nt < 4; nt++)
                wmma::mma_sync(oacc[0][nt], pa, bf[nt], oacc[0][nt]);
            if (mt1 < 13) {
                wmma::load_matrix_sync(pa, Ph + (mt1 * 16) * ALD + k * 16, ALD);
#pragma unroll
                for (int nt = 0; nt < 4; nt++)
                    wmma::mma_sync(oacc[1][nt], pa, bf[nt], oacc[1][nt]);
            }
        }
        __syncthreads();
    }

#pragma unroll
    for (int nt = 0; nt < 4; nt++) {
        wmma::store_matrix_sync(S + (mt0 * 16) * SLD + nt * 16, oacc[0][nt], SLD,
                                wmma::mem_row_major);
        if (mt1 < 13)
            wmma::store_matrix_sync(S + (mt1 * 16) * SLD + nt * 16, oacc[1][nt], SLD,
                                    wmma::mem_row_major);
    }
    __syncthreads();
    if (tid < Nsp) {
        const float inv = 1.f / rsum;
        const float* orow = &S[tid * SLD];
        float* dst = &Qg[(size_t)(base + tid) * DHd];
#pragma unroll
        for (int c = 0; c < 64; c += 4) {
            float4 v = *(const float4*)&orow[c];
            v.x *= inv; v.y *= inv; v.z *= inv; v.w *= inv;
            *(float4*)&dst[c] = v;
        }
    }
}

// ---------------------------------------------------------------------------
// cls attention (fp32 SIMT, unchanged)
// ---------------------------------------------------------------------------
__global__ __launch_bounds__(256) void attn_cls() {
    __shared__ __align__(16) float qs[64];
    __shared__ __align__(16) float red[256];
    __shared__ __align__(16) float outp[4][64];
    __shared__ __align__(16) float sc[Ntok];
    const int bh = blockIdx.x;
    const float* Kg = g_k + (size_t)bh * Ntok * DHd;
    const float* Vg = g_v + (size_t)bh * Ntok * DHd;
    const int tid = threadIdx.x;

    if (tid < 16) {
        float4 v = *(const float4*)&g_q[(size_t)bh * Ntok * DHd + tid * 4];
        *(float4*)&qs[tid * 4] = v;
    }
    __syncthreads();

    float lmax = -1e30f;
    for (int k = tid; k < Ntok; k += 256) {
        const float* kr = &Kg[(size_t)k * DHd];
        float s = 0.f;
#pragma unroll
        for (int d = 0; d < 64; d += 4) {
            float4 kv = *(const float4*)&kr[d];
            s += qs[d] * kv.x + qs[d + 1] * kv.y + qs[d + 2] * kv.z + qs[d + 3] * kv.w;
        }
        s *= 0.125f;
        sc[k] = s;
        lmax = fmaxf(lmax, s);
    }
    red[tid] = lmax;
    __syncthreads();
    for (int s2 = 128; s2 > 0; s2 >>= 1) {
        if (tid < s2) red[tid] = fmaxf(red[tid], red[tid + s2]);
        __syncthreads();
    }
    const float mx = red[0];
    __syncthreads();

    float lsum = 0.f;
    for (int k = tid; k < Ntok; k += 256) {
        float e = __expf(sc[k] - mx);
        sc[k] = e;
        lsum += e;
    }
    red[tid] = lsum;
    __syncthreads();
    for (int s2 = 128; s2 > 0; s2 >>= 1) {
        if (tid < s2) red[tid] += red[tid + s2];
        __syncthreads();
    }
    const float inv = 1.f / red[0];

    const int dh = tid & 63, seg = tid >> 6;
    float acc = 0.f;
    for (int k = seg; k < Ntok; k += 4)
        acc += sc[k] * Vg[(size_t)k * DHd + dh];
    outp[seg][dh] = acc;
    __syncthreads();
    if (tid < 64) {
        float o = (outp[0][tid] + outp[1][tid] + outp[2][tid] + outp[3][tid]) * inv;
        g_q[(size_t)bh * Ntok * DHd + tid] = o;
    }
}

// ---------------------------------------------------------------------------
extern "C" void kernel_launch(void* const* d_in, const int* in_sizes, int n_in,
                              void* d_out, int out_size) {
    const float* x     = (const float*)d_in[0];
    const float* w_qkv = (const float*)d_in[1];
    const float* w_out = (const float*)d_in[2];
    const float* b_out = (const float*)d_in[3];
    (void)in_sizes; (void)n_in; (void)out_size;

    cudaFuncSetAttribute(qkv_tc, cudaFuncAttributeMaxDynamicSharedMemorySize, GEMM_SMEM);
    cudaFuncSetAttribute(out_tc, cudaFuncAttributeMaxDynamicSharedMemorySize, GEMM_SMEM);
    cudaFuncSetAttribute(attn_spatial_tc, cudaFuncAttributeMaxDynamicSharedMemorySize,
                         (int)ATTN_SMEM);

    // conversions: inputs are true device pointers; destinations are device
    // globals referenced inside the kernels (never passed from host).
    conv_x <<<(unsigned)(((size_t)Mrows * KDIM) / (8 * 256)), 256>>>(x);
    conv_wq<<<(unsigned)(((size_t)O3 * KDIM) / (8 * 256)), 256>>>(w_qkv);
    conv_wo<<<(unsigned)(((size_t)DIM * KDIM) / (8 * 256)), 256>>>(w_out);

    dim3 g1(O3 / 256, (Mrows + 127) / 128);
    qkv_tc<<<g1, 256, GEMM_SMEM>>>();

    attn_spatial_tc<<<BH * Ff, 256, ATTN_SMEM>>>();
    attn_cls<<<BH, 256>>>();

    conv_attn<<<(unsigned)(((size_t)Mrows * KDIM) / (8 * 256)), 256>>>();

    dim3 g2(DIM / 256, (Mrows + 127) / 128);
    out_tc<<<g2, 256, GEMM_SMEM>>>(b_out, (float*)d_out);
}

// round 17
// speedup vs baseline: 3.5017x; 1.0693x over previous
#include <cuda_runtime.h>
#include <cuda_fp16.h>
#include <mma.h>
#include <cstdint>
#include <stdint.h>
#include <math.h>

using namespace nvcuda;

#define Bb    8
#define Hh    16
#define DHd   64
#define Ff    16
#define Nsp   196
#define Ntok  3137          // 1 + 16*196
#define DIM   1024
#define BH    (Bb*Hh)       // 128
#define Mrows (Bb*Ntok)     // 25096
#define O3    (3*DIM)       // 3072
#define KDIM  1024
#define KCH   64
#define NCHUNK (KDIM/KCH)   // 16

// ---------------- device scratch (allocation is forbidden) ------------------
// Referenced ONLY from device code (host-side use of __device__ symbols passes
// the host shadow address — the R12-R15 failure mode).
// g_xh/g_xl double as the attention-output hi/lo buffers (dead after qkv_tc).
__device__ __align__(16) float g_q[(size_t)BH*Ntok*DHd];
__device__ __align__(16) float g_k[(size_t)BH*Ntok*DHd];
__device__ __align__(16) float g_v[(size_t)BH*Ntok*DHd];
__device__ __align__(16) __half g_xh[(size_t)Mrows*KDIM];
__device__ __align__(16) __half g_xl[(size_t)Mrows*KDIM];
__device__ __align__(16) __half g_wqh[(size_t)O3*KDIM];
__device__ __align__(16) __half g_woh[(size_t)DIM*KDIM];

// ---------------- helpers ---------------------------------------------------
__device__ __forceinline__ uint32_t smem_u32(const void* p) {
    uint32_t a;
    asm("{ .reg .u64 t; cvta.to.shared.u64 t, %1; cvt.u32.u64 %0, t; }"
        : "=r"(a) : "l"(p));
    return a;
}
__device__ __forceinline__ void cp16(uint32_t dst, const void* src) {
    asm volatile("cp.async.cg.shared.global [%0], [%1], 16;" :: "r"(dst), "l"(src));
}
#define CP_COMMIT() asm volatile("cp.async.commit_group;" ::: "memory")
#define CP_WAIT1()  asm volatile("cp.async.wait_group 1;" ::: "memory")
#define CP_WAIT0()  asm volatile("cp.async.wait_group 0;" ::: "memory")

__device__ __forceinline__ void pack8hl(const float4 a, const float4 b, uint4& H, uint4& L) {
    float v[8] = {a.x, a.y, a.z, a.w, b.x, b.y, b.z, b.w};
    unsigned short hs[8], ls[8];
#pragma unroll
    for (int j = 0; j < 8; j++) {
        __half h = __float2half(v[j]);
        __half l = __float2half(v[j] - __half2float(h));
        hs[j] = __half_as_ushort(h);
        ls[j] = __half_as_ushort(l);
    }
    H.x = hs[0] | ((uint32_t)hs[1] << 16); H.y = hs[2] | ((uint32_t)hs[3] << 16);
    H.z = hs[4] | ((uint32_t)hs[5] << 16); H.w = hs[6] | ((uint32_t)hs[7] << 16);
    L.x = ls[0] | ((uint32_t)ls[1] << 16); L.y = ls[2] | ((uint32_t)ls[3] << 16);
    L.z = ls[4] | ((uint32_t)ls[5] << 16); L.w = ls[6] | ((uint32_t)ls[7] << 16);
}
__device__ __forceinline__ uint4 pack8h(const float4 a, const float4 b) {
    float v[8] = {a.x, a.y, a.z, a.w, b.x, b.y, b.z, b.w};
    unsigned short hs[8];
#pragma unroll
    for (int j = 0; j < 8; j++)
        hs[j] = __half_as_ushort(__float2half(v[j]));
    uint4 H;
    H.x = hs[0] | ((uint32_t)hs[1] << 16); H.y = hs[2] | ((uint32_t)hs[3] << 16);
    H.z = hs[4] | ((uint32_t)hs[5] << 16); H.w = hs[6] | ((uint32_t)hs[7] << 16);
    return H;
}

// ---------------- conversion kernels (globals referenced in DEVICE code) ----
__global__ __launch_bounds__(256) void conv_x(const float* __restrict__ s) {
    size_t i = ((size_t)blockIdx.x * 256 + threadIdx.x) * 8;
    if (i >= (size_t)Mrows * KDIM) return;
    float4 a = *(const float4*)(s + i);
    float4 b = *(const float4*)(s + i + 4);
    uint4 H, L;
    pack8hl(a, b, H, L);
    *(uint4*)(g_xh + i) = H;
    *(uint4*)(g_xl + i) = L;
}
__global__ __launch_bounds__(256) void conv_wq(const float* __restrict__ s) {
    size_t i = ((size_t)blockIdx.x * 256 + threadIdx.x) * 8;
    if (i >= (size_t)O3 * KDIM) return;
    float4 a = *(const float4*)(s + i);
    float4 b = *(const float4*)(s + i + 4);
    *(uint4*)(g_wqh + i) = pack8h(a, b);
}
__global__ __launch_bounds__(256) void conv_wo(const float* __restrict__ s) {
    size_t i = ((size_t)blockIdx.x * 256 + threadIdx.x) * 8;
    if (i >= (size_t)DIM * KDIM) return;
    float4 a = *(const float4*)(s + i);
    float4 b = *(const float4*)(s + i + 4);
    *(uint4*)(g_woh + i) = pack8h(a, b);
}

// ============================================================================
// Projection GEMMs: pure cp.async mainloop, KCH=64 (16 chunks, 4 ks-iters)
// ============================================================================
#define LDT     72
#define A_TILE_B (128 * LDT * 2)                 // 18432
#define B_TILE_B (256 * LDT * 2)                 // 36864
#define OFF_AHI  0
#define OFF_ALO  (A_TILE_B)
#define OFF_BHI  (2 * A_TILE_B)
#define STAGE_B  (2 * A_TILE_B + B_TILE_B)       // 73728
#define GEMM_SMEM (2 * STAGE_B)                  // 147456
#define CLD 132

#define GEMM_FILL(buf, c) do {                                                \
        uint32_t sb_ = smb + (buf) * STAGE_B;                                 \
        int ko_ = (c) * KCH;                                                  \
        _Pragma("unroll")                                                     \
        for (int i_ = 0; i_ < 4; i_++) {                                      \
            uint32_t so_ = soA_ + (uint32_t)i_ * (32 * LDT * 2);              \
            cp16(sb_ + OFF_AHI + so_, AhBase_ + rowA_[i_] + ko_);             \
            cp16(sb_ + OFF_ALO + so_, AlBase_ + rowA_[i_] + ko_);             \
        }                                                                     \
        _Pragma("unroll")                                                     \
        for (int i_ = 0; i_ < 8; i_++)                                        \
            cp16(sb_ + OFF_BHI + soA_ + (uint32_t)i_ * (32 * LDT * 2),        \
                 b0_ + ko_ + (size_t)i_ * 32 * KDIM);                         \
        CP_COMMIT();                                                          \
    } while (0)

// Declares + fills wmma accumulators acc[4][4] for a 128x256 C tile.
// A: row-major [m][1024] fp16 hi/lo. B: row-major [n][1024] fp16.
// Requires in scope: tid, wid, wm, wn, mBase, nBase, dsm.
#define GEMM_MAINLOOP(AhG, AlG, BhG)                                          \
    const uint32_t smb = smem_u32(dsm);                                       \
    const int r_ = tid >> 3;                                                  \
    const int g8_ = (tid & 7) * 8;                                            \
    const __half* AhBase_ = (AhG);                                            \
    const __half* AlBase_ = (AlG);                                            \
    size_t rowA_[4];                                                          \
    _Pragma("unroll")                                                         \
    for (int i_ = 0; i_ < 4; i_++) {                                          \
        int m_ = mBase + r_ + 32 * i_;                                        \
        if (m_ >= Mrows) m_ = Mrows - 1;                                      \
        rowA_[i_] = (size_t)m_ * KDIM + g8_;                                  \
    }                                                                         \
    const __half* b0_ = (BhG) + (size_t)(nBase + r_) * KDIM + g8_;            \
    const uint32_t soA_ = (uint32_t)(r_ * LDT + g8_) * 2;                     \
    wmma::fragment<wmma::accumulator,16,16,16,float> acc[4][4];               \
    _Pragma("unroll")                                                         \
    for (int mt = 0; mt < 4; mt++)                                            \
        _Pragma("unroll")                                                     \
        for (int nt = 0; nt < 4; nt++)                                        \
            wmma::fill_fragment(acc[mt][nt], 0.0f);                           \
    GEMM_FILL(0, 0);                                                          \
    GEMM_FILL(1, 1);                                                          \
    for (int c = 0; c < NCHUNK; c++) {                                        \
        const int b = c & 1;                                                  \
        if (c < NCHUNK - 1) CP_WAIT1(); else CP_WAIT0();                      \
        __syncthreads();                                                      \
        const __half* Ah = (const __half*)(dsm + b * STAGE_B + OFF_AHI);      \
        const __half* Al = (const __half*)(dsm + b * STAGE_B + OFF_ALO);      \
        const __half* Bh = (const __half*)(dsm + b * STAGE_B + OFF_BHI);      \
        _Pragma("unroll")                                                     \
        for (int ks = 0; ks < KCH; ks += 16) {                                \
            wmma::fragment<wmma::matrix_b,16,16,16,__half,wmma::col_major> bf[4]; \
            _Pragma("unroll")                                                 \
            for (int nt = 0; nt < 4; nt++)                                    \
                wmma::load_matrix_sync(bf[nt], Bh + (wn * 64 + nt * 16) * LDT + ks, LDT); \
            _Pragma("unroll")                                                 \
            for (int mt = 0; mt < 4; mt++) {                                  \
                wmma::fragment<wmma::matrix_a,16,16,16,__half,wmma::row_major> ah, al; \
                wmma::load_matrix_sync(ah, Ah + (wm * 64 + mt * 16) * LDT + ks, LDT); \
                wmma::load_matrix_sync(al, Al + (wm * 64 + mt * 16) * LDT + ks, LDT); \
                _Pragma("unroll")                                             \
                for (int nt = 0; nt < 4; nt++) {                              \
                    wmma::mma_sync(acc[mt][nt], ah, bf[nt], acc[mt][nt]);     \
                    wmma::mma_sync(acc[mt][nt], al, bf[nt], acc[mt][nt]);     \
                }                                                             \
            }                                                                 \
        }                                                                     \
        __syncthreads();                                                      \
        if (c + 2 < NCHUNK) GEMM_FILL(b, c + 2);                              \
    }

// ---------------- Kernel: qkv GEMM + head scatter ---------------------------
__global__ __launch_bounds__(256) void qkv_tc() {
    extern __shared__ __align__(16) char dsm[];
    const int tid = threadIdx.x;
    const int wid = tid >> 5;
    const int wm = wid >> 2, wn = wid & 3;
    const int mBase = blockIdx.y * 128;
    const int nBase = blockIdx.x * 256;

    GEMM_MAINLOOP(g_xh, g_xl, g_wqh)

    const int which = nBase >> 10;
    float* dst = (which == 0) ? g_q : (which == 1) ? g_k : g_v;
    float* Cs = (float*)dsm;

#pragma unroll
    for (int half = 0; half < 2; half++) {
        __syncthreads();
        if ((wn >> 1) == half) {
#pragma unroll
            for (int mt = 0; mt < 4; mt++)
#pragma unroll
                for (int nt = 0; nt < 4; nt++)
                    wmma::store_matrix_sync(Cs + (wm * 64 + mt * 16) * CLD +
                                            (wn & 1) * 64 + nt * 16,
                                            acc[mt][nt], CLD, wmma::mem_row_major);
        }
        __syncthreads();
#pragma unroll
        for (int i = 0; i < 16; i++) {
            int f4 = tid + i * 256;
            int row = f4 >> 5;
            int col = (f4 & 31) * 4;
            int m = mBase + row;
            if (m >= Mrows) continue;
            int b = m / Ntok, t = m - b * Ntok;
            int o = nBase + half * 128 + col;
            int h = (o & 1023) >> 6, dh = o & 63;
            const float* cp = Cs + row * CLD + col;
            float4 v = make_float4(cp[0], cp[1], cp[2], cp[3]);
            *(float4*)&dst[(((size_t)(b * Hh + h)) * Ntok + t) * DHd + dh] = v;
        }
    }
}

// ---------------- Kernel: out GEMM (A = attn hi/lo in g_xh/g_xl) + bias -----
__global__ __launch_bounds__(256) void out_tc(const float* __restrict__ bias,
                                              float* __restrict__ out) {
    extern __shared__ __align__(16) char dsm[];
    const int tid = threadIdx.x;
    const int wid = tid >> 5;
    const int wm = wid >> 2, wn = wid & 3;
    const int mBase = blockIdx.y * 128;
    const int nBase = blockIdx.x * 256;

    GEMM_MAINLOOP(g_xh, g_xl, g_woh)

    float* Cs = (float*)dsm;
#pragma unroll
    for (int half = 0; half < 2; half++) {
        __syncthreads();
        if ((wn >> 1) == half) {
#pragma unroll
            for (int mt = 0; mt < 4; mt++)
#pragma unroll
                for (int nt = 0; nt < 4; nt++)
                    wmma::store_matrix_sync(Cs + (wm * 64 + mt * 16) * CLD +
                                            (wn & 1) * 64 + nt * 16,
                                            acc[mt][nt], CLD, wmma::mem_row_major);
        }
        __syncthreads();
#pragma unroll
        for (int i = 0; i < 16; i++) {
            int f4 = tid + i * 256;
            int row = f4 >> 5;
            int col = (f4 & 31) * 4;
            int m = mBase + row;
            if (m >= Mrows) continue;
            int o = nBase + half * 128 + col;
            const float* cp = Cs + row * CLD + col;
            float4 v;
            v.x = cp[0] + bias[o];
            v.y = cp[1] + bias[o + 1];
            v.z = cp[2] + bias[o + 2];
            v.w = cp[3] + bias[o + 3];
            *(float4*)&out[(size_t)m * DIM + o] = v;
        }
    }
}

// ============================================================================
// Spatial attention — wmma, panelized, no-max softmax; epilogue writes
// row-major fp16 hi/lo directly into g_xh/g_xl (dead after qkv_tc).
// ============================================================================
#define AM   208
#define ALD  72
#define SLD  68
#define KP   64
#define NPAN 4

#define AOFF_QH 0
#define AOFF_QL (AOFF_QH + AM*ALD*2)
#define AOFF_KH (AOFF_QL + AM*ALD*2)
#define AOFF_VH (AOFF_KH + KP*ALD*2)
#define AOFF_PH (AOFF_VH + KP*ALD*2)
#define AOFF_S  (AOFF_PH + AM*ALD*2)
#define ATTN_SMEM (AOFF_S + AM*SLD*4)

__device__ __forceinline__ uint2 pack4h(float4 v) {
    unsigned short h0 = __half_as_ushort(__float2half(v.x));
    unsigned short h1 = __half_as_ushort(__float2half(v.y));
    unsigned short h2 = __half_as_ushort(__float2half(v.z));
    unsigned short h3 = __half_as_ushort(__float2half(v.w));
    uint2 r;
    r.x = h0 | ((uint32_t)h1 << 16);
    r.y = h2 | ((uint32_t)h3 << 16);
    return r;
}
__device__ __forceinline__ void pack4hl(float4 v, uint2& H, uint2& L) {
    float f[4] = {v.x, v.y, v.z, v.w};
    unsigned short hs[4], ls[4];
#pragma unroll
    for (int j = 0; j < 4; j++) {
        __half h = __float2half(f[j]);
        __half l = __float2half(f[j] - __half2float(h));
        hs[j] = __half_as_ushort(h);
        ls[j] = __half_as_ushort(l);
    }
    H.x = hs[0] | ((uint32_t)hs[1] << 16); H.y = hs[2] | ((uint32_t)hs[3] << 16);
    L.x = ls[0] | ((uint32_t)ls[1] << 16); L.y = ls[2] | ((uint32_t)ls[3] << 16);
}

__global__ __launch_bounds__(256) void attn_spatial_tc() {
    extern __shared__ __align__(16) char smb[];
    __half* Qh = (__half*)(smb + AOFF_QH);
    __half* Ql = (__half*)(smb + AOFF_QL);
    __half* Kh = (__half*)(smb + AOFF_KH);
    __half* Vh = (__half*)(smb + AOFF_VH);
    __half* Ph = (__half*)(smb + AOFF_PH);
    float*  S  = (float*)(smb + AOFF_S);

    const int bid = blockIdx.x;
    const int bh = bid >> 4, fi = bid & 15;
    const int base = 1 + fi * Nsp;
    const float* Kg = g_k + (size_t)bh * Ntok * DHd;
    const float* Vg = g_v + (size_t)bh * Ntok * DHd;
    const float* Qg = g_q + (size_t)bh * Ntok * DHd;
    const int tid = threadIdx.x;
    const int wid = tid >> 5;

    for (int idx = tid; idx < AM * 16; idx += 256) {
        int r = idx >> 4;
        int c4 = (idx & 15) * 4;
        float4 v = make_float4(0.f, 0.f, 0.f, 0.f);
        if (r < Nsp) v = *(const float4*)&Qg[(size_t)(base + r) * DHd + c4];
        uint2 H, L;
        pack4hl(v, H, L);
        *(uint2*)&Qh[r * ALD + c4] = H;
        *(uint2*)&Ql[r * ALD + c4] = L;
    }

    float rsum = 0.f;
    wmma::fragment<wmma::accumulator,16,16,16,float> oacc[2][4];
#pragma unroll
    for (int i = 0; i < 2; i++)
#pragma unroll
        for (int nt = 0; nt < 4; nt++)
            wmma::fill_fragment(oacc[i][nt], 0.0f);
    const int mt0 = wid;
    const int mt1 = 8 + wid;

    __syncthreads();

    for (int p = 0; p < NPAN; p++) {
        for (int idx = tid; idx < KP * 16; idx += 256) {
            int j = idx >> 4;
            int c4 = (idx & 15) * 4;
            int gk = p * KP + j;
            float4 kv = make_float4(0.f, 0.f, 0.f, 0.f);
            float4 vv = make_float4(0.f, 0.f, 0.f, 0.f);
            if (gk < 197) {
                int tok = (gk == 0) ? 0 : base + gk - 1;
                kv = *(const float4*)&Kg[(size_t)tok * DHd + c4];
                vv = *(const float4*)&Vg[(size_t)tok * DHd + c4];
            }
            *(uint2*)&Kh[j * ALD + c4] = pack4h(kv);
            *(uint2*)&Vh[j * ALD + c4] = pack4h(vv);
        }
        __syncthreads();

        for (int job = wid; job < 52; job += 8) {
            int mt = job >> 2, nt = job & 3;
            wmma::fragment<wmma::accumulator,16,16,16,float> sacc;
            wmma::fill_fragment(sacc, 0.0f);
#pragma unroll
            for (int k = 0; k < 4; k++) {
                wmma::fragment<wmma::matrix_a,16,16,16,__half,wmma::row_major> ah, al;
                wmma::fragment<wmma::matrix_b,16,16,16,__half,wmma::col_major> bf;
                wmma::load_matrix_sync(bf, Kh + (nt * 16) * ALD + k * 16, ALD);
                wmma::load_matrix_sync(ah, Qh + (mt * 16) * ALD + k * 16, ALD);
                wmma::load_matrix_sync(al, Ql + (mt * 16) * ALD + k * 16, ALD);
                wmma::mma_sync(sacc, ah, bf, sacc);
                wmma::mma_sync(sacc, al, bf, sacc);
            }
            wmma::store_matrix_sync(S + (mt * 16) * SLD + nt * 16, sacc, SLD,
                                    wmma::mem_row_major);
        }
        __syncthreads();

        if (tid < AM) {
            const int r = tid;
            const bool rok = (r < Nsp);
            float lsum = 0.f;
#pragma unroll 4
            for (int j = 0; j < KP; j += 4) {
                float4 s4 = *(const float4*)&S[r * SLD + j];
                int gk = p * KP + j;
                float e0 = (rok && gk + 0 < 197) ? __expf(s4.x * 0.125f) : 0.f;
                float e1 = (rok && gk + 1 < 197) ? __expf(s4.y * 0.125f) : 0.f;
                float e2 = (rok && gk + 2 < 197) ? __expf(s4.z * 0.125f) : 0.f;
                float e3 = (rok && gk + 3 < 197) ? __expf(s4.w * 0.125f) : 0.f;
                lsum += e0 + e1 + e2 + e3;
                uint2 P = pack4h(make_float4(e0, e1, e2, e3));
                *(uint2*)&Ph[r * ALD + j] = P;
            }
            rsum += lsum;
        }
        __syncthreads();

#pragma unroll
        for (int k = 0; k < 4; k++) {
            wmma::fragment<wmma::matrix_b,16,16,16,__half,wmma::row_major> bf[4];
#pragma unroll
            for (int nt = 0; nt < 4; nt++)
                wmma::load_matrix_sync(bf[nt], Vh + (k * 16) * ALD + nt * 16, ALD);
            wmma::fragment<wmma::matrix_a,16,16,16,__half,wmma::row_major> pa;
            wmma::load_matrix_sync(pa, Ph + (mt0 * 16) * ALD + k * 16, ALD);
#pragma unroll
            for (int nt = 0; nt < 4; nt++)
                wmma::mma_sync(oacc[0][nt], pa, bf[nt], oacc[0][nt]);
            if (mt1 < 13) {
                wmma::load_matrix_sync(pa, Ph + (mt1 * 16) * ALD + k * 16, ALD);
#pragma unroll
                for (int nt = 0; nt < 4; nt++)
                    wmma::mma_sync(oacc[1][nt], pa, bf[nt], oacc[1][nt]);
            }
        }
        __syncthreads();
    }

#pragma unroll
    for (int nt = 0; nt < 4; nt++) {
        wmma::store_matrix_sync(S + (mt0 * 16) * SLD + nt * 16, oacc[0][nt], SLD,
                                wmma::mem_row_major);
        if (mt1 < 13)
            wmma::store_matrix_sync(S + (mt1 * 16) * SLD + nt * 16, oacc[1][nt], SLD,
                                    wmma::mem_row_major);
    }
    __syncthreads();
    if (tid < Nsp) {
        const float inv = 1.f / rsum;
        const int bb = bh >> 4, h = bh & 15;
        const size_t off = (size_t)(bb * Ntok + base + tid) * KDIM + h * 64;
        const float* orow = &S[tid * SLD];
#pragma unroll
        for (int c = 0; c < 64; c += 4) {
            float4 v = *(const float4*)&orow[c];
            v.x *= inv; v.y *= inv; v.z *= inv; v.w *= inv;
            uint2 H, L;
            pack4hl(v, H, L);
            *(uint2*)&g_xh[off + c] = H;
            *(uint2*)&g_xl[off + c] = L;
        }
    }
}

// ---------------------------------------------------------------------------
// cls attention (fp32 SIMT); writes hi/lo fp16 into g_xh/g_xl row b*Ntok
// ---------------------------------------------------------------------------
__global__ __launch_bounds__(256) void attn_cls() {
    __shared__ __align__(16) float qs[64];
    __shared__ __align__(16) float red[256];
    __shared__ __align__(16) float outp[4][64];
    __shared__ __align__(16) float ofin[64];
    __shared__ __align__(16) float sc[Ntok];
    const int bh = blockIdx.x;
    const float* Kg = g_k + (size_t)bh * Ntok * DHd;
    const float* Vg = g_v + (size_t)bh * Ntok * DHd;
    const int tid = threadIdx.x;

    if (tid < 16) {
        float4 v = *(const float4*)&g_q[(size_t)bh * Ntok * DHd + tid * 4];
        *(float4*)&qs[tid * 4] = v;
    }
    __syncthreads();

    float lmax = -1e30f;
    for (int k = tid; k < Ntok; k += 256) {
        const float* kr = &Kg[(size_t)k * DHd];
        float s = 0.f;
#pragma unroll
        for (int d = 0; d < 64; d += 4) {
            float4 kv = *(const float4*)&kr[d];
            s += qs[d] * kv.x + qs[d + 1] * kv.y + qs[d + 2] * kv.z + qs[d + 3] * kv.w;
        }
        s *= 0.125f;
        sc[k] = s;
        lmax = fmaxf(lmax, s);
    }
    red[tid] = lmax;
    __syncthreads();
    for (int s2 = 128; s2 > 0; s2 >>= 1) {
        if (tid < s2) red[tid] = fmaxf(red[tid], red[tid + s2]);
        __syncthreads();
    }
    const float mx = red[0];
    __syncthreads();

    float lsum = 0.f;
    for (int k = tid; k < Ntok; k += 256) {
        float e = __expf(sc[k] - mx);
        sc[k] = e;
        lsum += e;
    }
    red[tid] = lsum;
    __syncthreads();
    for (int s2 = 128; s2 > 0; s2 >>= 1) {
        if (tid < s2) red[tid] += red[tid + s2];
        __syncthreads();
    }
    const float inv = 1.f / red[0];

    const int dh = tid & 63, seg = tid >> 6;
    float acc = 0.f;
    for (int k = seg; k < Ntok; k += 4)
        acc += sc[k] * Vg[(size_t)k * DHd + dh];
    outp[seg][dh] = acc;
    __syncthreads();
    if (tid < 64)
        ofin[tid] = (outp[0][tid] + outp[1][tid] + outp[2][tid] + outp[3][tid]) * inv;
    __syncthreads();
    if (tid < 16) {
        const int bb = bh >> 4, h = bh & 15;
        const size_t off = (size_t)(bb * Ntok) * KDIM + h * 64 + tid * 4;
        float4 v = *(const float4*)&ofin[tid * 4];
        uint2 H, L;
        pack4hl(v, H, L);
        *(uint2*)&g_xh[off] = H;
        *(uint2*)&g_xl[off] = L;
    }
}

// ---------------------------------------------------------------------------
extern "C" void kernel_launch(void* const* d_in, const int* in_sizes, int n_in,
                              void* d_out, int out_size) {
    const float* x     = (const float*)d_in[0];
    const float* w_qkv = (const float*)d_in[1];
    const float* w_out = (const float*)d_in[2];
    const float* b_out = (const float*)d_in[3];
    (void)in_sizes; (void)n_in; (void)out_size;

    cudaFuncSetAttribute(qkv_tc, cudaFuncAttributeMaxDynamicSharedMemorySize, GEMM_SMEM);
    cudaFuncSetAttribute(out_tc, cudaFuncAttributeMaxDynamicSharedMemorySize, GEMM_SMEM);
    cudaFuncSetAttribute(attn_spatial_tc, cudaFuncAttributeMaxDynamicSharedMemorySize,
                         (int)ATTN_SMEM);

    conv_x <<<(unsigned)(((size_t)Mrows * KDIM) / (8 * 256)), 256>>>(x);
    conv_wq<<<(unsigned)(((size_t)O3 * KDIM) / (8 * 256)), 256>>>(w_qkv);
    conv_wo<<<(unsigned)(((size_t)DIM * KDIM) / (8 * 256)), 256>>>(w_out);

    dim3 g1(O3 / 256, (Mrows + 127) / 128);
    qkv_tc<<<g1, 256, GEMM_SMEM>>>();

    attn_spatial_tc<<<BH * Ff, 256, ATTN_SMEM>>>();
    attn_cls<<<BH, 256>>>();

    dim3 g2(DIM / 256, (Mrows + 127) / 128);
    out_tc<<<g2, 256, GEMM_SMEM>>>(b_out, (float*)d_out);
}